// round 6
// baseline (speedup 1.0000x reference)
#include <cuda_runtime.h>
#include <cuda_bf16.h>
#include <math.h>
#include <stdint.h>

// SparseMoE: T=2048, D=1024, F=4096, E=8, top-2.
// router -> gather+split tokens to bf16 hi/lo planes -> grouped GEMM1
// (bf16x3 mma.sync, B=W1 fp32 converted in-kernel, relu, writes h planes)
// -> grouped GEMM2 (B=W2 fp32 in-kernel, gate) -> combine.

#define D_DIM 1024
#define E_NUM 8
#define F_DIM 4096
#define MAXT  2048
#define MAXROWS (2 * MAXT)

// -------------------- device scratch (no cudaMalloc allowed) ---------------
__device__ __nv_bfloat16 g_xh[(size_t)MAXROWS * D_DIM];
__device__ __nv_bfloat16 g_xl[(size_t)MAXROWS * D_DIM];
__device__ __nv_bfloat16 g_hh[(size_t)MAXROWS * F_DIM];
__device__ __nv_bfloat16 g_hl[(size_t)MAXROWS * F_DIM];
__device__ float g_y[(size_t)MAXROWS * D_DIM];
__device__ int   g_cnt[E_NUM];
__device__ int   g_off[E_NUM];
__device__ int   g_topi[MAXT * 2];
__device__ float g_gate[MAXT * 2];
__device__ int   g_pos[MAXT * 2];
__device__ int   g_slot[MAXT * 2];
__device__ int   g_rowtok[MAXROWS];
__device__ float g_rowgate[MAXROWS];

// -------------------- helpers ----------------------------------------------
__device__ __forceinline__ uint32_t smem_u32(const void* p) {
    uint32_t a;
    asm("{ .reg .u64 t; cvta.to.shared.u64 t, %1; cvt.u32.u64 %0, t; }"
        : "=r"(a) : "l"(p));
    return a;
}

#define SW128(o) ((uint32_t)(o) ^ ((((uint32_t)(o)) >> 3) & 0x70u))

#define CPASYNC16(s, g) \
    asm volatile("cp.async.cg.shared.global [%0], [%1], 16;" \
        :: "r"((uint32_t)(s)), "l"(g) : "memory")
#define CPCOMMIT() asm volatile("cp.async.commit_group;" ::: "memory")

__device__ __forceinline__ void ldsm_x4(uint32_t* r, uint32_t addr) {
    asm volatile("ldmatrix.sync.aligned.m8n8.x4.shared.b16 {%0,%1,%2,%3}, [%4];"
        : "=r"(r[0]), "=r"(r[1]), "=r"(r[2]), "=r"(r[3]) : "r"(addr));
}
__device__ __forceinline__ void ldsm_x4_t(uint32_t* r, uint32_t addr) {
    asm volatile("ldmatrix.sync.aligned.m8n8.x4.trans.shared.b16 {%0,%1,%2,%3}, [%4];"
        : "=r"(r[0]), "=r"(r[1]), "=r"(r[2]), "=r"(r[3]) : "r"(addr));
}
__device__ __forceinline__ void mma16816(float* c, const uint32_t* a,
                                         uint32_t b0, uint32_t b1) {
    asm volatile(
        "mma.sync.aligned.m16n8k16.row.col.f32.bf16.bf16.f32 "
        "{%0,%1,%2,%3}, {%4,%5,%6,%7}, {%8,%9}, {%0,%1,%2,%3};"
        : "+f"(c[0]), "+f"(c[1]), "+f"(c[2]), "+f"(c[3])
        : "r"(a[0]), "r"(a[1]), "r"(a[2]), "r"(a[3]), "r"(b0), "r"(b1));
}

// pack two fp32 -> (hi bf16x2, lo bf16x2)
__device__ __forceinline__ uint32_t pack2(float a, float b, uint32_t& lo2) {
    __nv_bfloat16 ha = __float2bfloat16_rn(a);
    __nv_bfloat16 hb = __float2bfloat16_rn(b);
    __nv_bfloat16 la = __float2bfloat16_rn(a - __bfloat162float(ha));
    __nv_bfloat16 lb = __float2bfloat16_rn(b - __bfloat162float(hb));
    lo2 = (uint32_t)*(unsigned short*)&la | ((uint32_t)*(unsigned short*)&lb << 16);
    return (uint32_t)*(unsigned short*)&ha | ((uint32_t)*(unsigned short*)&hb << 16);
}

// -------------------- router ------------------------------------------------
__global__ void zero_cnt_kernel() {
    if (threadIdx.x < E_NUM) g_cnt[threadIdx.x] = 0;
}

__global__ void router_kernel(const float* __restrict__ x,
                              const float* __restrict__ Wn,
                              const float* __restrict__ bn, int T) {
    int gw   = (blockIdx.x * blockDim.x + threadIdx.x) >> 5;
    int lane = threadIdx.x & 31;
    if (gw >= T) return;
    const float* xr = x + (size_t)gw * D_DIM;
    float acc[E_NUM];
#pragma unroll
    for (int e = 0; e < E_NUM; e++) acc[e] = 0.f;
    for (int d = lane; d < D_DIM; d += 32) {
        float xv = xr[d];
#pragma unroll
        for (int e = 0; e < E_NUM; e++) acc[e] += xv * Wn[d * E_NUM + e];
    }
#pragma unroll
    for (int off = 16; off; off >>= 1)
#pragma unroll
        for (int e = 0; e < E_NUM; e++)
            acc[e] += __shfl_xor_sync(0xffffffffu, acc[e], off);

    if (lane == 0) {
        float v[E_NUM];
#pragma unroll
        for (int e = 0; e < E_NUM; e++) v[e] = acc[e] + bn[e];
        int i0 = 0;
#pragma unroll
        for (int e = 1; e < E_NUM; e++) if (v[e] > v[i0]) i0 = e;
        int i1 = (i0 == 0) ? 1 : 0;
#pragma unroll
        for (int e = 0; e < E_NUM; e++)
            if (e != i0 && v[e] > v[i1]) i1 = e;
        float ex = expf(v[i1] - v[i0]);
        float g0 = 1.f / (1.f + ex);
        float g1 = ex / (1.f + ex);
        int p0 = atomicAdd(&g_cnt[i0], 1);
        int p1 = atomicAdd(&g_cnt[i1], 1);
        int b = gw * 2;
        g_topi[b] = i0; g_topi[b + 1] = i1;
        g_gate[b] = g0; g_gate[b + 1] = g1;
        g_pos[b]  = p0; g_pos[b + 1]  = p1;
    }
}

__global__ void scan_kernel() {
    if (threadIdx.x == 0) {
        int s = 0;
        for (int e = 0; e < E_NUM; e++) { g_off[e] = s; s += g_cnt[e]; }
    }
}

__global__ void build_kernel(int T) {
    int i = blockIdx.x * blockDim.x + threadIdx.x;
    if (i >= T * 2) return;
    int e = g_topi[i];
    int slot = g_off[e] + g_pos[i];
    g_slot[i] = slot;
    g_rowtok[slot]  = i >> 1;
    g_rowgate[slot] = g_gate[i];
}

__global__ void gatherx_kernel(const float* __restrict__ x) {
    int slot = blockIdx.x;
    int d = threadIdx.x * 4;
    float4 v = *(const float4*)(x + (size_t)g_rowtok[slot] * D_DIM + d);
    uint32_t l0, l1;
    uint32_t h0 = pack2(v.x, v.y, l0);
    uint32_t h1 = pack2(v.z, v.w, l1);
    size_t o = ((size_t)slot * D_DIM + d) >> 2;
    ((uint2*)g_xh)[o] = make_uint2(h0, h1);
    ((uint2*)g_xl)[o] = make_uint2(l0, l1);
}

// -------------------- grouped GEMM (bf16x3 mma.sync) ------------------------
// C[slot, n] = epi( A[slot, :K] @ B_e[:K, n] + bias_e[n] )
// A planes: bf16 [slot][K] (precomputed) ; B: fp32 [E][K][N], converted to
// bf16 hi/lo planes in-kernel (register prefetch one chunk ahead).
// Tile 128x128, K-chunk 64, 512 thr (16 warps, 4x4), double-buffered smem.
#define AHI_OFF 0
#define ALO_OFF 16384
#define BHI_OFF 32768
#define BLO_OFF 49152
#define STAGE_BYTES 65536
#define SMEM_DYN (2 * STAGE_BYTES)

template<int KDIM, int NDIM, bool RELU>
__global__ __launch_bounds__(512, 1)
void moe_gemm_kernel(const __nv_bfloat16* __restrict__ Ahi,
                     const __nv_bfloat16* __restrict__ Alo,
                     const float* __restrict__ Bf,      // fp32 weights
                     const float* __restrict__ bias,
                     __nv_bfloat16* __restrict__ Chi,   // GEMM1 out (hi plane)
                     __nv_bfloat16* __restrict__ Clo,   // GEMM1 out (lo plane)
                     float* __restrict__ Cf) {          // GEMM2 out (fp32)
    const int e   = blockIdx.z;
    const int cnt = g_cnt[e];
    const int m0  = blockIdx.y * 128;
    if (m0 >= cnt) return;
    const int base = g_off[e];
    const int n0   = blockIdx.x * 128;
    const int tid  = threadIdx.x;
    const int wid  = tid >> 5;
    const int lane = tid & 31;
    const int wm   = wid & 3;    // warp row (32 rows)
    const int wn   = wid >> 2;   // warp col (32 cols)

    extern __shared__ char smem[];
    const uint32_t sb = smem_u32(smem);

    const float* Be = Bf + (size_t)e * KDIM * NDIM;

    // ---- A staging via cp.async: 2 x 16B per plane per thread
    size_t a_go[2];
    uint32_t a_sw[2];
#pragma unroll
    for (int i = 0; i < 2; i++) {
        int idx = tid + i * 512;
        int ar = idx >> 3, kg = idx & 7;           // 128 rows x 8 chunks of 16B
        int am = m0 + ar; if (am >= cnt) am = cnt - 1;
        a_go[i] = (size_t)(base + am) * KDIM + kg * 8;
        a_sw[i] = SW128(ar * 128 + kg * 16);
    }
    auto issueA = [&](int c) {
        uint32_t st = sb + (c & 1) * STAGE_BYTES;
        const __nv_bfloat16* pah = Ahi + (size_t)c * 64;
        const __nv_bfloat16* pal = Alo + (size_t)c * 64;
#pragma unroll
        for (int i = 0; i < 2; i++) {
            CPASYNC16(st + AHI_OFF + a_sw[i], pah + a_go[i]);
            CPASYNC16(st + ALO_OFF + a_sw[i], pal + a_go[i]);
        }
        CPCOMMIT();
    };

    // ---- B fp32 register prefetch: 2 halves x 8 floats per thread
    // half h: k = tid>>3 (0..63), ng = tid&7, n byte col = (h*64 + ng*8)
    const int bk  = tid >> 3;
    const int bng = tid & 7;
    const float* bptr0 = Be + (size_t)bk * NDIM + n0 + bng * 8;
    const float* bptr1 = bptr0 + 64;
    uint32_t b_sts0 = SW128((uint32_t)(bk * 128 + bng * 16));
    uint32_t b_sts1 = b_sts0 + 8192;

    float4 breg[2][2];   // [half][2x float4]
    auto ldgB = [&](int c) {
        const float* p0 = bptr0 + (size_t)c * 64 * NDIM;
        const float* p1 = bptr1 + (size_t)c * 64 * NDIM;
        breg[0][0] = __ldg((const float4*)p0);
        breg[0][1] = __ldg((const float4*)p0 + 1);
        breg[1][0] = __ldg((const float4*)p1);
        breg[1][1] = __ldg((const float4*)p1 + 1);
    };
    auto stsB = [&](int c) {
        uint32_t st = sb + (c & 1) * STAGE_BYTES;
#pragma unroll
        for (int h = 0; h < 2; h++) {
            uint32_t hi[4], lo[4];
            hi[0] = pack2(breg[h][0].x, breg[h][0].y, lo[0]);
            hi[1] = pack2(breg[h][0].z, breg[h][0].w, lo[1]);
            hi[2] = pack2(breg[h][1].x, breg[h][1].y, lo[2]);
            hi[3] = pack2(breg[h][1].z, breg[h][1].w, lo[3]);
            uint32_t off = (h == 0) ? b_sts0 : b_sts1;
            asm volatile("st.shared.v4.b32 [%0], {%1,%2,%3,%4};"
                :: "r"(st + BHI_OFF + off), "r"(hi[0]), "r"(hi[1]), "r"(hi[2]), "r"(hi[3]));
            asm volatile("st.shared.v4.b32 [%0], {%1,%2,%3,%4};"
                :: "r"(st + BLO_OFF + off), "r"(lo[0]), "r"(lo[1]), "r"(lo[2]), "r"(lo[3]));
        }
    };

    float C[2][4][4];
#pragma unroll
    for (int i = 0; i < 2; i++)
#pragma unroll
        for (int j = 0; j < 4; j++)
#pragma unroll
            for (int q = 0; q < 4; q++) C[i][j][q] = 0.f;

    constexpr int CHUNKS = KDIM / 64;
    const int g  = lane >> 3;       // ldmatrix lane group
    const int lr = lane & 7;
    const int bhalf = wn >> 1;      // B smem half (cols 0-63 / 64-127)

    issueA(0);
    ldgB(0);
    for (int c = 0; c < CHUNKS; c++) {
        __syncthreads();            // buffer (c&1) free of prior readers
        stsB(c);                    // convert regs -> planes[(c)&1]
        if (c + 1 < CHUNKS) {
            ldgB(c + 1);            // prefetch next chunk (hides under MMA)
            issueA(c + 1);
            asm volatile("cp.async.wait_group 1;" ::: "memory");  // A(c) done
        } else {
            asm volatile("cp.async.wait_group 0;" ::: "memory");
        }
        __syncthreads();            // planes + A visible to all
        uint32_t st = sb + (c & 1) * STAGE_BYTES;

#pragma unroll
        for (int ks = 0; ks < 4; ks++) {
            uint32_t a[2][2][4];    // [mtile][plane][4]
#pragma unroll
            for (int mt = 0; mt < 2; mt++) {
                int row = wm * 32 + mt * 16 + (g & 1) * 8 + lr;
                int col = ks * 16 + (g >> 1) * 8;
                uint32_t off = SW128(row * 128 + col * 2);
                ldsm_x4(a[mt][0], st + AHI_OFF + off);
                ldsm_x4(a[mt][1], st + ALO_OFF + off);
            }
            uint32_t b[2][2][4];    // [n16][plane][4] = 2 n8 frags each
#pragma unroll
            for (int nt = 0; nt < 2; nt++) {
                int kk = ks * 16 + (g & 1) * 8 + lr;
                int nn = (wn & 1) * 32 + nt * 16 + (g >> 1) * 8;
                uint32_t off = bhalf * 8192 + SW128(kk * 128 + nn * 2);
                ldsm_x4_t(b[nt][0], st + BHI_OFF + off);
                ldsm_x4_t(b[nt][1], st + BLO_OFF + off);
            }
            // combos: hi*hi, hi*lo, lo*hi
#pragma unroll
            for (int q = 0; q < 3; q++) {
                const int ap = (q == 2) ? 1 : 0;
                const int bp = (q == 1) ? 1 : 0;
#pragma unroll
                for (int mt = 0; mt < 2; mt++)
#pragma unroll
                    for (int nt = 0; nt < 2; nt++)
#pragma unroll
                        for (int s = 0; s < 2; s++)
                            mma16816(C[mt][nt * 2 + s], a[mt][ap],
                                     b[nt][bp][s * 2], b[nt][bp][s * 2 + 1]);
            }
        }
    }

    // -------- epilogue
    const int qr = lane >> 2, qc = lane & 3;
#pragma unroll
    for (int mt = 0; mt < 2; mt++) {
#pragma unroll
        for (int j = 0; j < 4; j++) {
            int col = n0 + wn * 32 + j * 8 + qc * 2;
            float b0 = bias[e * NDIM + col];
            float b1 = bias[e * NDIM + col + 1];
#pragma unroll
            for (int h = 0; h < 2; h++) {
                int lrow = wm * 32 + mt * 16 + qr + h * 8;
                if (m0 + lrow >= cnt) continue;
                int gr = base + m0 + lrow;
                float v0 = C[mt][j][h * 2 + 0] + b0;
                float v1 = C[mt][j][h * 2 + 1] + b1;
                if (RELU) {
                    v0 = v0 > 0.f ? v0 : 0.f;
                    v1 = v1 > 0.f ? v1 : 0.f;
                    uint32_t lo2;
                    uint32_t hi2 = pack2(v0, v1, lo2);
                    size_t o = ((size_t)gr * NDIM + col) >> 1;
                    ((uint32_t*)Chi)[o] = hi2;
                    ((uint32_t*)Clo)[o] = lo2;
                } else {
                    float gate = g_rowgate[gr];
                    float2 o2 = make_float2(gate * v0, gate * v1);
                    *(float2*)(Cf + (size_t)gr * NDIM + col) = o2;
                }
            }
        }
    }
}

// -------------------- combine ----------------------------------------------
__global__ void combine_kernel(float* __restrict__ out, int T) {
    int i = blockIdx.x * blockDim.x + threadIdx.x;
    if (i >= T * D_DIM) return;
    int t = i >> 10;
    int d = i & (D_DIM - 1);
    out[i] = g_y[(size_t)g_slot[t * 2] * D_DIM + d] +
             g_y[(size_t)g_slot[t * 2 + 1] * D_DIM + d];
}

// -------------------- launch ------------------------------------------------
extern "C" void kernel_launch(void* const* d_in, const int* in_sizes, int n_in,
                              void* d_out, int out_size) {
    const float* x  = (const float*)d_in[0];
    const float* Wn = (const float*)d_in[1];
    const float* bn = (const float*)d_in[2];
    const float* W1 = (const float*)d_in[3];
    const float* b1 = (const float*)d_in[4];
    const float* W2 = (const float*)d_in[5];
    const float* b2 = (const float*)d_in[6];
    const int T = in_sizes[0] / D_DIM;

    cudaFuncSetAttribute(moe_gemm_kernel<D_DIM, F_DIM, true>,
                         cudaFuncAttributeMaxDynamicSharedMemorySize, SMEM_DYN);
    cudaFuncSetAttribute(moe_gemm_kernel<F_DIM, D_DIM, false>,
                         cudaFuncAttributeMaxDynamicSharedMemorySize, SMEM_DYN);

    __nv_bfloat16 *xh, *xl, *hh, *hl;
    float* yptr;
    cudaGetSymbolAddress((void**)&xh, g_xh);
    cudaGetSymbolAddress((void**)&xl, g_xl);
    cudaGetSymbolAddress((void**)&hh, g_hh);
    cudaGetSymbolAddress((void**)&hl, g_hl);
    cudaGetSymbolAddress((void**)&yptr, g_y);

    zero_cnt_kernel<<<1, 32>>>();
    router_kernel<<<(T * 32 + 255) / 256, 256>>>(x, Wn, bn, T);
    scan_kernel<<<1, 32>>>();
    build_kernel<<<(T * 2 + 255) / 256, 256>>>(T);
    gatherx_kernel<<<T * 2, 256>>>(x);

    const int MT = (MAXT + 127) / 128;  // worst case: one expert takes all tokens
    dim3 g1(F_DIM / 128, MT, E_NUM);
    moe_gemm_kernel<D_DIM, F_DIM, true><<<g1, 512, SMEM_DYN>>>(
        xh, xl, W1, b1, hh, hl, nullptr);
    dim3 g2(D_DIM / 128, MT, E_NUM);
    moe_gemm_kernel<F_DIM, D_DIM, false><<<g2, 512, SMEM_DYN>>>(
        hh, hl, W2, b2, nullptr, nullptr, yptr);

    combine_kernel<<<(T * D_DIM + 255) / 256, 256>>>((float*)d_out, T);
}

// round 7
// speedup vs baseline: 1.0473x; 1.0473x over previous
#include <cuda_runtime.h>
#include <cuda_bf16.h>
#include <math.h>
#include <stdint.h>

// SparseMoE: T=2048, D=1024, F=4096, E=8, top-2.
// router -> convert weights to bf16 hi/lo planes -> gather+split tokens ->
// grouped GEMM1 (bf16x3 mma.sync, relu, writes h planes) ->
// grouped GEMM2 split-K=4 (partial planes, gate folded) -> combine(+bias2).

#define D_DIM 1024
#define E_NUM 8
#define F_DIM 4096
#define MAXT  2048
#define MAXROWS (2 * MAXT)
#define SPLITK2 4

// -------------------- device scratch (no cudaMalloc allowed) ---------------
__device__ __nv_bfloat16 g_w1h[(size_t)E_NUM * D_DIM * F_DIM];
__device__ __nv_bfloat16 g_w1l[(size_t)E_NUM * D_DIM * F_DIM];
__device__ __nv_bfloat16 g_w2h[(size_t)E_NUM * F_DIM * D_DIM];
__device__ __nv_bfloat16 g_w2l[(size_t)E_NUM * F_DIM * D_DIM];
__device__ __nv_bfloat16 g_xh[(size_t)MAXROWS * D_DIM];
__device__ __nv_bfloat16 g_xl[(size_t)MAXROWS * D_DIM];
__device__ __nv_bfloat16 g_hh[(size_t)MAXROWS * F_DIM];
__device__ __nv_bfloat16 g_hl[(size_t)MAXROWS * F_DIM];
__device__ float g_yp[(size_t)SPLITK2 * MAXROWS * D_DIM];   // split-K partials
__device__ int   g_cnt[E_NUM];
__device__ int   g_off[E_NUM];
__device__ int   g_topi[MAXT * 2];
__device__ float g_gate[MAXT * 2];
__device__ int   g_pos[MAXT * 2];
__device__ int   g_slot[MAXT * 2];
__device__ int   g_rowtok[MAXROWS];
__device__ float g_rowgate[MAXROWS];

// -------------------- helpers ----------------------------------------------
__device__ __forceinline__ uint32_t smem_u32(const void* p) {
    uint32_t a;
    asm("{ .reg .u64 t; cvta.to.shared.u64 t, %1; cvt.u32.u64 %0, t; }"
        : "=r"(a) : "l"(p));
    return a;
}

#define SW128(o) ((uint32_t)(o) ^ ((((uint32_t)(o)) >> 3) & 0x70u))

#define CPASYNC16(s, g) \
    asm volatile("cp.async.cg.shared.global [%0], [%1], 16;" \
        :: "r"((uint32_t)(s)), "l"(g) : "memory")
#define CPCOMMIT() asm volatile("cp.async.commit_group;" ::: "memory")

__device__ __forceinline__ void ldsm_x4(uint32_t* r, uint32_t addr) {
    asm volatile("ldmatrix.sync.aligned.m8n8.x4.shared.b16 {%0,%1,%2,%3}, [%4];"
        : "=r"(r[0]), "=r"(r[1]), "=r"(r[2]), "=r"(r[3]) : "r"(addr));
}
__device__ __forceinline__ void ldsm_x4_t(uint32_t* r, uint32_t addr) {
    asm volatile("ldmatrix.sync.aligned.m8n8.x4.trans.shared.b16 {%0,%1,%2,%3}, [%4];"
        : "=r"(r[0]), "=r"(r[1]), "=r"(r[2]), "=r"(r[3]) : "r"(addr));
}
__device__ __forceinline__ void mma16816(float* c, const uint32_t* a,
                                         uint32_t b0, uint32_t b1) {
    asm volatile(
        "mma.sync.aligned.m16n8k16.row.col.f32.bf16.bf16.f32 "
        "{%0,%1,%2,%3}, {%4,%5,%6,%7}, {%8,%9}, {%0,%1,%2,%3};"
        : "+f"(c[0]), "+f"(c[1]), "+f"(c[2]), "+f"(c[3])
        : "r"(a[0]), "r"(a[1]), "r"(a[2]), "r"(a[3]), "r"(b0), "r"(b1));
}

// pack two fp32 -> (hi bf16x2, lo bf16x2)
__device__ __forceinline__ uint32_t pack2(float a, float b, uint32_t& lo2) {
    __nv_bfloat16 ha = __float2bfloat16_rn(a);
    __nv_bfloat16 hb = __float2bfloat16_rn(b);
    __nv_bfloat16 la = __float2bfloat16_rn(a - __bfloat162float(ha));
    __nv_bfloat16 lb = __float2bfloat16_rn(b - __bfloat162float(hb));
    lo2 = (uint32_t)*(unsigned short*)&la | ((uint32_t)*(unsigned short*)&lb << 16);
    return (uint32_t)*(unsigned short*)&ha | ((uint32_t)*(unsigned short*)&hb << 16);
}

// -------------------- router ------------------------------------------------
__global__ void zero_cnt_kernel() {
    if (threadIdx.x < E_NUM) g_cnt[threadIdx.x] = 0;
}

__global__ void router_kernel(const float* __restrict__ x,
                              const float* __restrict__ Wn,
                              const float* __restrict__ bn, int T) {
    int gw   = (blockIdx.x * blockDim.x + threadIdx.x) >> 5;
    int lane = threadIdx.x & 31;
    if (gw >= T) return;
    const float* xr = x + (size_t)gw * D_DIM;
    float acc[E_NUM];
#pragma unroll
    for (int e = 0; e < E_NUM; e++) acc[e] = 0.f;
    for (int d = lane; d < D_DIM; d += 32) {
        float xv = xr[d];
#pragma unroll
        for (int e = 0; e < E_NUM; e++) acc[e] += xv * Wn[d * E_NUM + e];
    }
#pragma unroll
    for (int off = 16; off; off >>= 1)
#pragma unroll
        for (int e = 0; e < E_NUM; e++)
            acc[e] += __shfl_xor_sync(0xffffffffu, acc[e], off);

    if (lane == 0) {
        float v[E_NUM];
#pragma unroll
        for (int e = 0; e < E_NUM; e++) v[e] = acc[e] + bn[e];
        int i0 = 0;
#pragma unroll
        for (int e = 1; e < E_NUM; e++) if (v[e] > v[i0]) i0 = e;
        int i1 = (i0 == 0) ? 1 : 0;
#pragma unroll
        for (int e = 0; e < E_NUM; e++)
            if (e != i0 && v[e] > v[i1]) i1 = e;
        float ex = expf(v[i1] - v[i0]);
        float g0 = 1.f / (1.f + ex);
        float g1 = ex / (1.f + ex);
        int p0 = atomicAdd(&g_cnt[i0], 1);
        int p1 = atomicAdd(&g_cnt[i1], 1);
        int b = gw * 2;
        g_topi[b] = i0; g_topi[b + 1] = i1;
        g_gate[b] = g0; g_gate[b + 1] = g1;
        g_pos[b]  = p0; g_pos[b + 1]  = p1;
    }
}

__global__ void scan_kernel() {
    if (threadIdx.x == 0) {
        int s = 0;
        for (int e = 0; e < E_NUM; e++) { g_off[e] = s; s += g_cnt[e]; }
    }
}

__global__ void build_kernel(int T) {
    int i = blockIdx.x * blockDim.x + threadIdx.x;
    if (i >= T * 2) return;
    int e = g_topi[i];
    int slot = g_off[e] + g_pos[i];
    g_slot[i] = slot;
    g_rowtok[slot]  = i >> 1;
    g_rowgate[slot] = g_gate[i];
}

// -------------------- conversions ------------------------------------------
__global__ void convert_kernel(const float* __restrict__ src,
                               __nv_bfloat16* __restrict__ hi,
                               __nv_bfloat16* __restrict__ lo, size_t n8) {
    size_t i = (size_t)blockIdx.x * blockDim.x + threadIdx.x;
    if (i >= n8) return;
    float4 v0 = ((const float4*)src)[i * 2];
    float4 v1 = ((const float4*)src)[i * 2 + 1];
    uint4 h, l;
    h.x = pack2(v0.x, v0.y, l.x);
    h.y = pack2(v0.z, v0.w, l.y);
    h.z = pack2(v1.x, v1.y, l.z);
    h.w = pack2(v1.z, v1.w, l.w);
    ((uint4*)hi)[i] = h;
    ((uint4*)lo)[i] = l;
}

__global__ void gatherx_kernel(const float* __restrict__ x) {
    int slot = blockIdx.x;
    int d = threadIdx.x * 4;
    float4 v = *(const float4*)(x + (size_t)g_rowtok[slot] * D_DIM + d);
    uint32_t l0, l1;
    uint32_t h0 = pack2(v.x, v.y, l0);
    uint32_t h1 = pack2(v.z, v.w, l1);
    size_t o = ((size_t)slot * D_DIM + d) >> 2;
    ((uint2*)g_xh)[o] = make_uint2(h0, h1);
    ((uint2*)g_xl)[o] = make_uint2(l0, l1);
}

// -------------------- grouped GEMM (bf16x3 mma.sync) ------------------------
// C[slot, n] = epi( A[slot, koff:koff+K/S] @ B_e[koff:, n] [+ bias] )
// Tile 128x128, K-chunk 64, 512 thr (16 warps, 4x4), double-buffered smem.
#define AHI_OFF 0
#define ALO_OFF 16384
#define BHI_OFF 32768
#define BLO_OFF 49152
#define STAGE_BYTES 65536
#define SMEM_DYN (2 * STAGE_BYTES)

template<int KDIM, int NDIM, bool RELU, int SPLITS>
__global__ __launch_bounds__(512, 1)
void moe_gemm_kernel(const __nv_bfloat16* __restrict__ Ahi,
                     const __nv_bfloat16* __restrict__ Alo,
                     const __nv_bfloat16* __restrict__ Bhi,
                     const __nv_bfloat16* __restrict__ Blo,
                     const float* __restrict__ bias,     // RELU path only
                     __nv_bfloat16* __restrict__ Chi,    // GEMM1 out (hi plane)
                     __nv_bfloat16* __restrict__ Clo,    // GEMM1 out (lo plane)
                     float* __restrict__ Cf) {           // GEMM2 partials base
    const int e   = blockIdx.z / SPLITS;
    const int sp  = blockIdx.z % SPLITS;
    const int cnt = g_cnt[e];
    const int m0  = blockIdx.y * 128;
    if (m0 >= cnt) return;
    const int base = g_off[e];
    const int n0   = blockIdx.x * 128;
    const int koff = sp * (KDIM / SPLITS);
    const int tid  = threadIdx.x;
    const int wid  = tid >> 5;
    const int lane = tid & 31;
    const int wm   = wid & 3;    // warp row (32 rows)
    const int wn   = wid >> 2;   // warp col (32 cols)

    extern __shared__ char smem[];
    const uint32_t sb = smem_u32(smem);

    const __nv_bfloat16* Behi = Bhi + (size_t)e * KDIM * NDIM;
    const __nv_bfloat16* Belo = Blo + (size_t)e * KDIM * NDIM;

    // staging assignments (2 x 16B per plane per thread)
    size_t a_go[2], b_go[2];
    uint32_t a_sw[2], b_sw[2];
#pragma unroll
    for (int i = 0; i < 2; i++) {
        int idx = tid + i * 512;
        int ar = idx >> 3, kg = idx & 7;           // A: 128 rows x 8 chunks
        int am = m0 + ar; if (am >= cnt) am = cnt - 1;
        a_go[i] = (size_t)(base + am) * KDIM + koff + kg * 8;
        a_sw[i] = SW128(ar * 128 + kg * 16);
        int bk = idx >> 4, bj = idx & 15;          // B: 64 k x 16 chunks
        int bh = bj >> 3, bn = bj & 7;
        b_go[i] = (size_t)bk * NDIM + n0 + bh * 64 + bn * 8;
        b_sw[i] = bh * 8192 + SW128(bk * 128 + bn * 16);
    }

    auto issue = [&](int c) {
        uint32_t st = sb + (c & 1) * STAGE_BYTES;
        const __nv_bfloat16* pah = Ahi + (size_t)c * 64;
        const __nv_bfloat16* pal = Alo + (size_t)c * 64;
        const __nv_bfloat16* pbh = Behi + (size_t)(koff + c * 64) * NDIM;
        const __nv_bfloat16* pbl = Belo + (size_t)(koff + c * 64) * NDIM;
#pragma unroll
        for (int i = 0; i < 2; i++) {
            CPASYNC16(st + AHI_OFF + a_sw[i], pah + a_go[i]);
            CPASYNC16(st + ALO_OFF + a_sw[i], pal + a_go[i]);
            CPASYNC16(st + BHI_OFF + b_sw[i], pbh + b_go[i]);
            CPASYNC16(st + BLO_OFF + b_sw[i], pbl + b_go[i]);
        }
        CPCOMMIT();
    };

    float C[2][4][4];
#pragma unroll
    for (int i = 0; i < 2; i++)
#pragma unroll
        for (int j = 0; j < 4; j++)
#pragma unroll
            for (int q = 0; q < 4; q++) C[i][j][q] = 0.f;

    constexpr int CHUNKS = KDIM / SPLITS / 64;
    const int g  = lane >> 3;       // ldmatrix lane group
    const int lr = lane & 7;
    const int bhalf = wn >> 1;      // B smem half (cols 0-63 / 64-127)

    issue(0);
    for (int c = 0; c < CHUNKS; c++) {
        if (c + 1 < CHUNKS) {
            issue(c + 1);
            asm volatile("cp.async.wait_group 1;" ::: "memory");
        } else {
            asm volatile("cp.async.wait_group 0;" ::: "memory");
        }
        __syncthreads();
        uint32_t st = sb + (c & 1) * STAGE_BYTES;

#pragma unroll
        for (int ks = 0; ks < 4; ks++) {
            uint32_t a[2][2][4];    // [mtile][plane][4]
#pragma unroll
            for (int mt = 0; mt < 2; mt++) {
                int row = wm * 32 + mt * 16 + (g & 1) * 8 + lr;
                int col = ks * 16 + (g >> 1) * 8;
                uint32_t off = SW128(row * 128 + col * 2);
                ldsm_x4(a[mt][0], st + AHI_OFF + off);
                ldsm_x4(a[mt][1], st + ALO_OFF + off);
            }
            uint32_t b[2][2][4];    // [n16][plane][4] = 2 n8 frags each
#pragma unroll
            for (int nt = 0; nt < 2; nt++) {
                int kk = ks * 16 + (g & 1) * 8 + lr;
                int nn = (wn & 1) * 32 + nt * 16 + (g >> 1) * 8;
                uint32_t off = bhalf * 8192 + SW128(kk * 128 + nn * 2);
                ldsm_x4_t(b[nt][0], st + BHI_OFF + off);
                ldsm_x4_t(b[nt][1], st + BLO_OFF + off);
            }
            // combos: hi*hi, hi*lo, lo*hi
#pragma unroll
            for (int q = 0; q < 3; q++) {
                const int ap = (q == 2) ? 1 : 0;
                const int bp = (q == 1) ? 1 : 0;
#pragma unroll
                for (int mt = 0; mt < 2; mt++)
#pragma unroll
                    for (int nt = 0; nt < 2; nt++)
#pragma unroll
                        for (int s = 0; s < 2; s++)
                            mma16816(C[mt][nt * 2 + s], a[mt][ap],
                                     b[nt][bp][s * 2], b[nt][bp][s * 2 + 1]);
            }
        }
        __syncthreads();
    }

    // -------- epilogue
    const int qr = lane >> 2, qc = lane & 3;
    float* Cpart = Cf + (size_t)sp * MAXROWS * NDIM;
#pragma unroll
    for (int mt = 0; mt < 2; mt++) {
#pragma unroll
        for (int j = 0; j < 4; j++) {
            int col = n0 + wn * 32 + j * 8 + qc * 2;
            float b0 = 0.f, b1 = 0.f;
            if (RELU) {
                b0 = bias[e * NDIM + col];
                b1 = bias[e * NDIM + col + 1];
            }
#pragma unroll
            for (int h = 0; h < 2; h++) {
                int lrow = wm * 32 + mt * 16 + qr + h * 8;
                if (m0 + lrow >= cnt) continue;
                int gr = base + m0 + lrow;
                float v0 = C[mt][j][h * 2 + 0] + b0;
                float v1 = C[mt][j][h * 2 + 1] + b1;
                if (RELU) {
                    v0 = v0 > 0.f ? v0 : 0.f;
                    v1 = v1 > 0.f ? v1 : 0.f;
                    uint32_t lo2;
                    uint32_t hi2 = pack2(v0, v1, lo2);
                    size_t o = ((size_t)gr * NDIM + col) >> 1;
                    ((uint32_t*)Chi)[o] = hi2;
                    ((uint32_t*)Clo)[o] = lo2;
                } else {
                    float gate = g_rowgate[gr];
                    float2 o2 = make_float2(gate * v0, gate * v1);
                    *(float2*)(Cpart + (size_t)gr * NDIM + col) = o2;
                }
            }
        }
    }
}

// -------------------- combine (sums split-K partials, adds gated bias2) ----
__global__ void combine_kernel(float* __restrict__ out,
                               const float* __restrict__ b2, int T) {
    int i = blockIdx.x * blockDim.x + threadIdx.x;          // float4 index
    if (i >= T * (D_DIM / 4)) return;
    int t  = i / (D_DIM / 4);
    int d4 = i - t * (D_DIM / 4);

    float4 acc = make_float4(0.f, 0.f, 0.f, 0.f);
#pragma unroll
    for (int p = 0; p < 2; p++) {
        int idx  = t * 2 + p;
        int slot = g_slot[idx];
        int e    = g_topi[idx];
        float gv = g_gate[idx];
        float4 bb = ((const float4*)(b2 + (size_t)e * D_DIM))[d4];
        acc.x += gv * bb.x; acc.y += gv * bb.y;
        acc.z += gv * bb.z; acc.w += gv * bb.w;
        size_t ro = (size_t)slot * (D_DIM / 4) + d4;
#pragma unroll
        for (int s = 0; s < SPLITK2; s++) {
            float4 v = ((const float4*)g_yp)[(size_t)s * MAXROWS * (D_DIM / 4) + ro];
            acc.x += v.x; acc.y += v.y; acc.z += v.z; acc.w += v.w;
        }
    }
    ((float4*)out)[i] = acc;
}

// -------------------- launch ------------------------------------------------
extern "C" void kernel_launch(void* const* d_in, const int* in_sizes, int n_in,
                              void* d_out, int out_size) {
    const float* x  = (const float*)d_in[0];
    const float* Wn = (const float*)d_in[1];
    const float* bn = (const float*)d_in[2];
    const float* W1 = (const float*)d_in[3];
    const float* b1 = (const float*)d_in[4];
    const float* W2 = (const float*)d_in[5];
    const float* b2 = (const float*)d_in[6];
    const int T = in_sizes[0] / D_DIM;

    cudaFuncSetAttribute(moe_gemm_kernel<D_DIM, F_DIM, true, 1>,
                         cudaFuncAttributeMaxDynamicSharedMemorySize, SMEM_DYN);
    cudaFuncSetAttribute(moe_gemm_kernel<F_DIM, D_DIM, false, SPLITK2>,
                         cudaFuncAttributeMaxDynamicSharedMemorySize, SMEM_DYN);

    __nv_bfloat16 *w1h, *w1l, *w2h, *w2l, *xh, *xl, *hh, *hl;
    float* ypptr;
    cudaGetSymbolAddress((void**)&w1h, g_w1h);
    cudaGetSymbolAddress((void**)&w1l, g_w1l);
    cudaGetSymbolAddress((void**)&w2h, g_w2h);
    cudaGetSymbolAddress((void**)&w2l, g_w2l);
    cudaGetSymbolAddress((void**)&xh, g_xh);
    cudaGetSymbolAddress((void**)&xl, g_xl);
    cudaGetSymbolAddress((void**)&hh, g_hh);
    cudaGetSymbolAddress((void**)&hl, g_hl);
    cudaGetSymbolAddress((void**)&ypptr, g_yp);

    zero_cnt_kernel<<<1, 32>>>();
    router_kernel<<<(T * 32 + 255) / 256, 256>>>(x, Wn, bn, T);
    scan_kernel<<<1, 32>>>();
    build_kernel<<<(T * 2 + 255) / 256, 256>>>(T);
    gatherx_kernel<<<T * 2, 256>>>(x);

    const size_t wn8 = (size_t)E_NUM * D_DIM * F_DIM / 8;
    convert_kernel<<<(unsigned)((wn8 + 255) / 256), 256>>>(W1, w1h, w1l, wn8);
    convert_kernel<<<(unsigned)((wn8 + 255) / 256), 256>>>(W2, w2h, w2l, wn8);

    const int MT = (MAXT + 127) / 128;  // worst case: one expert takes all tokens
    dim3 g1(F_DIM / 128, MT, E_NUM);
    moe_gemm_kernel<D_DIM, F_DIM, true, 1><<<g1, 512, SMEM_DYN>>>(
        xh, xl, w1h, w1l, b1, hh, hl, nullptr);
    dim3 g2(D_DIM / 128, MT, E_NUM * SPLITK2);
    moe_gemm_kernel<F_DIM, D_DIM, false, SPLITK2><<<g2, 512, SMEM_DYN>>>(
        hh, hl, w2h, w2l, nullptr, nullptr, nullptr, ypptr);

    combine_kernel<<<(T * (D_DIM / 4) + 255) / 256, 256>>>((float*)d_out, b2, T);
}

// round 8
// speedup vs baseline: 2.1831x; 2.0844x over previous
#include <cuda_runtime.h>
#include <cuda_fp16.h>
#include <math.h>
#include <stdint.h>

// SparseMoE: T=2048, D=1024, F=4096, E=8, top-2.
// router -> convert weights to fp16 -> gather tokens to fp16 ->
// grouped GEMM1 (fp16 mma.sync f32-acc, relu, fp16 h out) ->
// grouped GEMM2 (fp16, +bias, *gate) -> combine.

#define D_DIM 1024
#define E_NUM 8
#define F_DIM 4096
#define MAXT  2048
#define MAXROWS (2 * MAXT)

// -------------------- device scratch (no cudaMalloc allowed) ---------------
__device__ __half g_w1h[(size_t)E_NUM * D_DIM * F_DIM];
__device__ __half g_w2h[(size_t)E_NUM * F_DIM * D_DIM];
__device__ __half g_xh[(size_t)MAXROWS * D_DIM];
__device__ __half g_hh[(size_t)MAXROWS * F_DIM];
__device__ float g_y[(size_t)MAXROWS * D_DIM];
__device__ int   g_cnt[E_NUM];
__device__ int   g_off[E_NUM];
__device__ int   g_topi[MAXT * 2];
__device__ float g_gate[MAXT * 2];
__device__ int   g_pos[MAXT * 2];
__device__ int   g_slot[MAXT * 2];
__device__ int   g_rowtok[MAXROWS];
__device__ float g_rowgate[MAXROWS];

// -------------------- helpers ----------------------------------------------
__device__ __forceinline__ uint32_t smem_u32(const void* p) {
    uint32_t a;
    asm("{ .reg .u64 t; cvta.to.shared.u64 t, %1; cvt.u32.u64 %0, t; }"
        : "=r"(a) : "l"(p));
    return a;
}

#define SW128(o) ((uint32_t)(o) ^ ((((uint32_t)(o)) >> 3) & 0x70u))

#define CPASYNC16(s, g) \
    asm volatile("cp.async.cg.shared.global [%0], [%1], 16;" \
        :: "r"((uint32_t)(s)), "l"(g) : "memory")
#define CPCOMMIT() asm volatile("cp.async.commit_group;" ::: "memory")
#define CPWAIT2()  asm volatile("cp.async.wait_group 2;" ::: "memory")
#define CPWAIT1()  asm volatile("cp.async.wait_group 1;" ::: "memory")
#define CPWAIT0()  asm volatile("cp.async.wait_group 0;" ::: "memory")

__device__ __forceinline__ void ldsm_x4(uint32_t* r, uint32_t addr) {
    asm volatile("ldmatrix.sync.aligned.m8n8.x4.shared.b16 {%0,%1,%2,%3}, [%4];"
        : "=r"(r[0]), "=r"(r[1]), "=r"(r[2]), "=r"(r[3]) : "r"(addr));
}
__device__ __forceinline__ void ldsm_x4_t(uint32_t* r, uint32_t addr) {
    asm volatile("ldmatrix.sync.aligned.m8n8.x4.trans.shared.b16 {%0,%1,%2,%3}, [%4];"
        : "=r"(r[0]), "=r"(r[1]), "=r"(r[2]), "=r"(r[3]) : "r"(addr));
}
__device__ __forceinline__ void mma16816(float* c, const uint32_t* a,
                                         uint32_t b0, uint32_t b1) {
    asm volatile(
        "mma.sync.aligned.m16n8k16.row.col.f32.f16.f16.f32 "
        "{%0,%1,%2,%3}, {%4,%5,%6,%7}, {%8,%9}, {%0,%1,%2,%3};"
        : "+f"(c[0]), "+f"(c[1]), "+f"(c[2]), "+f"(c[3])
        : "r"(a[0]), "r"(a[1]), "r"(a[2]), "r"(a[3]), "r"(b0), "r"(b1));
}

__device__ __forceinline__ uint32_t pack2h(float a, float b) {
    __half2 h = __floats2half2_rn(a, b);
    return *(uint32_t*)&h;
}

// -------------------- router ------------------------------------------------
__global__ void zero_cnt_kernel() {
    if (threadIdx.x < E_NUM) g_cnt[threadIdx.x] = 0;
}

__global__ void router_kernel(const float* __restrict__ x,
                              const float* __restrict__ Wn,
                              const float* __restrict__ bn, int T) {
    int gw   = (blockIdx.x * blockDim.x + threadIdx.x) >> 5;
    int lane = threadIdx.x & 31;
    if (gw >= T) return;
    const float* xr = x + (size_t)gw * D_DIM;
    float acc[E_NUM];
#pragma unroll
    for (int e = 0; e < E_NUM; e++) acc[e] = 0.f;
    for (int d = lane; d < D_DIM; d += 32) {
        float xv = xr[d];
#pragma unroll
        for (int e = 0; e < E_NUM; e++) acc[e] += xv * Wn[d * E_NUM + e];
    }
#pragma unroll
    for (int off = 16; off; off >>= 1)
#pragma unroll
        for (int e = 0; e < E_NUM; e++)
            acc[e] += __shfl_xor_sync(0xffffffffu, acc[e], off);

    if (lane == 0) {
        float v[E_NUM];
#pragma unroll
        for (int e = 0; e < E_NUM; e++) v[e] = acc[e] + bn[e];
        int i0 = 0;
#pragma unroll
        for (int e = 1; e < E_NUM; e++) if (v[e] > v[i0]) i0 = e;
        int i1 = (i0 == 0) ? 1 : 0;
#pragma unroll
        for (int e = 0; e < E_NUM; e++)
            if (e != i0 && v[e] > v[i1]) i1 = e;
        float ex = expf(v[i1] - v[i0]);
        float g0 = 1.f / (1.f + ex);
        float g1 = ex / (1.f + ex);
        int p0 = atomicAdd(&g_cnt[i0], 1);
        int p1 = atomicAdd(&g_cnt[i1], 1);
        int b = gw * 2;
        g_topi[b] = i0; g_topi[b + 1] = i1;
        g_gate[b] = g0; g_gate[b + 1] = g1;
        g_pos[b]  = p0; g_pos[b + 1]  = p1;
    }
}

__global__ void scan_kernel() {
    if (threadIdx.x == 0) {
        int s = 0;
        for (int e = 0; e < E_NUM; e++) { g_off[e] = s; s += g_cnt[e]; }
    }
}

__global__ void build_kernel(int T) {
    int i = blockIdx.x * blockDim.x + threadIdx.x;
    if (i >= T * 2) return;
    int e = g_topi[i];
    int slot = g_off[e] + g_pos[i];
    g_slot[i] = slot;
    g_rowtok[slot]  = i >> 1;
    g_rowgate[slot] = g_gate[i];
}

// -------------------- conversions ------------------------------------------
__global__ void convert_kernel(const float* __restrict__ src,
                               __half* __restrict__ dst, size_t n8) {
    size_t i = (size_t)blockIdx.x * blockDim.x + threadIdx.x;
    if (i >= n8) return;
    float4 v0 = ((const float4*)src)[i * 2];
    float4 v1 = ((const float4*)src)[i * 2 + 1];
    uint4 h;
    h.x = pack2h(v0.x, v0.y);
    h.y = pack2h(v0.z, v0.w);
    h.z = pack2h(v1.x, v1.y);
    h.w = pack2h(v1.z, v1.w);
    ((uint4*)dst)[i] = h;
}

__global__ void gatherx_kernel(const float* __restrict__ x) {
    int slot = blockIdx.x;
    int d = threadIdx.x * 4;
    float4 v = *(const float4*)(x + (size_t)g_rowtok[slot] * D_DIM + d);
    uint2 h;
    h.x = pack2h(v.x, v.y);
    h.y = pack2h(v.z, v.w);
    ((uint2*)g_xh)[((size_t)slot * D_DIM + d) >> 2] = h;
}

// -------------------- grouped GEMM (fp16 mma.sync, f32 accum) ---------------
// C[slot, n] = epi( A[slot, :K] @ B_e[:K, n] + bias_e[n] )
// Tile 128x128, K-chunk 64, 512 thr (16 warps, 4x4), 4-stage cp.async ring.
#define A_OFF 0
#define B_OFF 16384
#define STAGE_BYTES 32768
#define NSTAGE 4
#define SMEM_DYN (NSTAGE * STAGE_BYTES)

template<int KDIM, int NDIM, bool RELU>
__global__ __launch_bounds__(512, 1)
void moe_gemm_kernel(const __half* __restrict__ Ah,
                     const __half* __restrict__ Bh,
                     const float* __restrict__ bias,
                     __half* __restrict__ Ch,    // GEMM1 out (fp16)
                     float* __restrict__ Cf) {   // GEMM2 out (fp32)
    const int e   = blockIdx.z;
    const int cnt = g_cnt[e];
    const int m0  = blockIdx.y * 128;
    if (m0 >= cnt) return;
    const int base = g_off[e];
    const int n0   = blockIdx.x * 128;
    const int tid  = threadIdx.x;
    const int wid  = tid >> 5;
    const int lane = tid & 31;
    const int wm   = wid & 3;    // warp row (32 rows)
    const int wn   = wid >> 2;   // warp col (32 cols)

    extern __shared__ char smem[];
    const uint32_t sb = smem_u32(smem);

    const __half* Be = Bh + (size_t)e * KDIM * NDIM;

    // staging assignments (2 x 16B per operand per thread)
    size_t a_go[2], b_go[2];
    uint32_t a_sw[2], b_sw[2];
#pragma unroll
    for (int i = 0; i < 2; i++) {
        int idx = tid + i * 512;
        int ar = idx >> 3, kg = idx & 7;           // A: 128 rows x 8 x 16B
        int am = m0 + ar; if (am >= cnt) am = cnt - 1;
        a_go[i] = (size_t)(base + am) * KDIM + kg * 8;
        a_sw[i] = SW128(ar * 128 + kg * 16);
        int bk = idx >> 4, bj = idx & 15;          // B: 64 k x 16 x 16B
        int bh = bj >> 3, bn = bj & 7;
        b_go[i] = (size_t)bk * NDIM + n0 + bh * 64 + bn * 8;
        b_sw[i] = bh * 8192 + SW128(bk * 128 + bn * 16);
    }

    auto issue = [&](int c) {
        uint32_t st = sb + (c & (NSTAGE - 1)) * STAGE_BYTES;
        const __half* pa = Ah + (size_t)c * 64;
        const __half* pb = Be + (size_t)c * 64 * NDIM;
#pragma unroll
        for (int i = 0; i < 2; i++) {
            CPASYNC16(st + A_OFF + a_sw[i], pa + a_go[i]);
            CPASYNC16(st + B_OFF + b_sw[i], pb + b_go[i]);
        }
        CPCOMMIT();
    };

    float C[2][4][4];
#pragma unroll
    for (int i = 0; i < 2; i++)
#pragma unroll
        for (int j = 0; j < 4; j++)
#pragma unroll
            for (int q = 0; q < 4; q++) C[i][j][q] = 0.f;

    constexpr int CHUNKS = KDIM / 64;
    const int g  = lane >> 3;       // ldmatrix lane group
    const int lr = lane & 7;
    const int bhalf = wn >> 1;      // B smem half (cols 0-63 / 64-127)

    issue(0); issue(1); issue(2);
    for (int c = 0; c < CHUNKS; c++) {
        const int rem = CHUNKS - 1 - c;      // stages still pending after c
        if (rem >= 2)      CPWAIT2();
        else if (rem == 1) CPWAIT1();
        else               CPWAIT0();
        __syncthreads();
        uint32_t st = sb + (c & (NSTAGE - 1)) * STAGE_BYTES;

#pragma unroll
        for (int ks = 0; ks < 4; ks++) {
            uint32_t a[2][4];
#pragma unroll
            for (int mt = 0; mt < 2; mt++) {
                int row = wm * 32 + mt * 16 + (g & 1) * 8 + lr;
                int col = ks * 16 + (g >> 1) * 8;
                ldsm_x4(a[mt], st + A_OFF + SW128(row * 128 + col * 2));
            }
            uint32_t b[2][4];
#pragma unroll
            for (int nt = 0; nt < 2; nt++) {
                int kk = ks * 16 + (g & 1) * 8 + lr;
                int nn = (wn & 1) * 32 + nt * 16 + (g >> 1) * 8;
                ldsm_x4_t(b[nt], st + B_OFF + bhalf * 8192 + SW128(kk * 128 + nn * 2));
            }
#pragma unroll
            for (int mt = 0; mt < 2; mt++)
#pragma unroll
                for (int nt = 0; nt < 2; nt++)
#pragma unroll
                    for (int s = 0; s < 2; s++)
                        mma16816(C[mt][nt * 2 + s], a[mt],
                                 b[nt][s * 2], b[nt][s * 2 + 1]);
        }
        if (c + 3 < CHUNKS) issue(c + 3);
    }

    // -------- epilogue
    const int qr = lane >> 2, qc = lane & 3;
#pragma unroll
    for (int mt = 0; mt < 2; mt++) {
#pragma unroll
        for (int j = 0; j < 4; j++) {
            int col = n0 + wn * 32 + j * 8 + qc * 2;
            float b0 = bias[e * NDIM + col];
            float b1 = bias[e * NDIM + col + 1];
#pragma unroll
            for (int h = 0; h < 2; h++) {
                int lrow = wm * 32 + mt * 16 + qr + h * 8;
                if (m0 + lrow >= cnt) continue;
                int gr = base + m0 + lrow;
                float v0 = C[mt][j][h * 2 + 0] + b0;
                float v1 = C[mt][j][h * 2 + 1] + b1;
                if (RELU) {
                    v0 = v0 > 0.f ? v0 : 0.f;
                    v1 = v1 > 0.f ? v1 : 0.f;
                    ((uint32_t*)Ch)[((size_t)gr * NDIM + col) >> 1] = pack2h(v0, v1);
                } else {
                    float gate = g_rowgate[gr];
                    float2 o2 = make_float2(gate * v0, gate * v1);
                    *(float2*)(Cf + (size_t)gr * NDIM + col) = o2;
                }
            }
        }
    }
}

// -------------------- combine ----------------------------------------------
__global__ void combine_kernel(float* __restrict__ out, int T) {
    int i = blockIdx.x * blockDim.x + threadIdx.x;          // float4 index
    if (i >= T * (D_DIM / 4)) return;
    int t  = i >> 8;                 // / (D_DIM/4)
    int d4 = i & (D_DIM / 4 - 1);
    size_t r0 = (size_t)g_slot[t * 2]     * (D_DIM / 4) + d4;
    size_t r1 = (size_t)g_slot[t * 2 + 1] * (D_DIM / 4) + d4;
    float4 a = ((const float4*)g_y)[r0];
    float4 b = ((const float4*)g_y)[r1];
    ((float4*)out)[i] = make_float4(a.x + b.x, a.y + b.y, a.z + b.z, a.w + b.w);
}

// -------------------- launch ------------------------------------------------
extern "C" void kernel_launch(void* const* d_in, const int* in_sizes, int n_in,
                              void* d_out, int out_size) {
    const float* x  = (const float*)d_in[0];
    const float* Wn = (const float*)d_in[1];
    const float* bn = (const float*)d_in[2];
    const float* W1 = (const float*)d_in[3];
    const float* b1 = (const float*)d_in[4];
    const float* W2 = (const float*)d_in[5];
    const float* b2 = (const float*)d_in[6];
    const int T = in_sizes[0] / D_DIM;

    cudaFuncSetAttribute(moe_gemm_kernel<D_DIM, F_DIM, true>,
                         cudaFuncAttributeMaxDynamicSharedMemorySize, SMEM_DYN);
    cudaFuncSetAttribute(moe_gemm_kernel<F_DIM, D_DIM, false>,
                         cudaFuncAttributeMaxDynamicSharedMemorySize, SMEM_DYN);

    __half *w1h, *w2h, *xh, *hh;
    float* yptr;
    cudaGetSymbolAddress((void**)&w1h, g_w1h);
    cudaGetSymbolAddress((void**)&w2h, g_w2h);
    cudaGetSymbolAddress((void**)&xh, g_xh);
    cudaGetSymbolAddress((void**)&hh, g_hh);
    cudaGetSymbolAddress((void**)&yptr, g_y);

    zero_cnt_kernel<<<1, 32>>>();
    router_kernel<<<(T * 32 + 255) / 256, 256>>>(x, Wn, bn, T);
    scan_kernel<<<1, 32>>>();
    build_kernel<<<(T * 2 + 255) / 256, 256>>>(T);
    gatherx_kernel<<<T * 2, 256>>>(x);

    const size_t wn8 = (size_t)E_NUM * D_DIM * F_DIM / 8;
    convert_kernel<<<(unsigned)((wn8 + 255) / 256), 256>>>(W1, w1h, wn8);
    convert_kernel<<<(unsigned)((wn8 + 255) / 256), 256>>>(W2, w2h, wn8);

    const int MT = (MAXT + 127) / 128;  // worst case: one expert takes all tokens
    dim3 g1(F_DIM / 128, MT, E_NUM);
    moe_gemm_kernel<D_DIM, F_DIM, true><<<g1, 512, SMEM_DYN>>>(
        xh, w1h, b1, hh, nullptr);
    dim3 g2(D_DIM / 128, MT, E_NUM);
    moe_gemm_kernel<F_DIM, D_DIM, false><<<g2, 512, SMEM_DYN>>>(
        hh, w2h, b2, nullptr, yptr);

    combine_kernel<<<(T * (D_DIM / 4) + 255) / 256, 256>>>((float*)d_out, T);
}

// round 9
// speedup vs baseline: 2.4111x; 1.1044x over previous
#include <cuda_runtime.h>
#include <cuda_fp16.h>
#include <math.h>
#include <stdint.h>

// SparseMoE: T=2048, D=1024, F=4096, E=8, top-2.
// router -> convert weights to fp16 -> gather tokens to fp16 ->
// grouped GEMM1 (fp16 mma.sync f32-acc, relu, fp16 h out) ->
// grouped GEMM2 (fp16, +bias, *gate) -> combine.
// GEMM: 128x128 tile, 256 thr (8 warps, 2x4, 64x32/warp), 3-stage ring,
// 2 CTAs/SM.

#define D_DIM 1024
#define E_NUM 8
#define F_DIM 4096
#define MAXT  2048
#define MAXROWS (2 * MAXT)

// -------------------- device scratch (no cudaMalloc allowed) ---------------
__device__ __half g_w1h[(size_t)E_NUM * D_DIM * F_DIM];
__device__ __half g_w2h[(size_t)E_NUM * F_DIM * D_DIM];
__device__ __half g_xh[(size_t)MAXROWS * D_DIM];
__device__ __half g_hh[(size_t)MAXROWS * F_DIM];
__device__ float g_y[(size_t)MAXROWS * D_DIM];
__device__ int   g_cnt[E_NUM];
__device__ int   g_off[E_NUM];
__device__ int   g_topi[MAXT * 2];
__device__ float g_gate[MAXT * 2];
__device__ int   g_pos[MAXT * 2];
__device__ int   g_slot[MAXT * 2];
__device__ int   g_rowtok[MAXROWS];
__device__ float g_rowgate[MAXROWS];

// -------------------- helpers ----------------------------------------------
__device__ __forceinline__ uint32_t smem_u32(const void* p) {
    uint32_t a;
    asm("{ .reg .u64 t; cvta.to.shared.u64 t, %1; cvt.u32.u64 %0, t; }"
        : "=r"(a) : "l"(p));
    return a;
}

#define SW128(o) ((uint32_t)(o) ^ ((((uint32_t)(o)) >> 3) & 0x70u))

#define CPASYNC16(s, g) \
    asm volatile("cp.async.cg.shared.global [%0], [%1], 16;" \
        :: "r"((uint32_t)(s)), "l"(g) : "memory")
#define CPCOMMIT() asm volatile("cp.async.commit_group;" ::: "memory")
#define CPWAIT1()  asm volatile("cp.async.wait_group 1;" ::: "memory")
#define CPWAIT0()  asm volatile("cp.async.wait_group 0;" ::: "memory")

__device__ __forceinline__ void ldsm_x4(uint32_t* r, uint32_t addr) {
    asm volatile("ldmatrix.sync.aligned.m8n8.x4.shared.b16 {%0,%1,%2,%3}, [%4];"
        : "=r"(r[0]), "=r"(r[1]), "=r"(r[2]), "=r"(r[3]) : "r"(addr));
}
__device__ __forceinline__ void ldsm_x4_t(uint32_t* r, uint32_t addr) {
    asm volatile("ldmatrix.sync.aligned.m8n8.x4.trans.shared.b16 {%0,%1,%2,%3}, [%4];"
        : "=r"(r[0]), "=r"(r[1]), "=r"(r[2]), "=r"(r[3]) : "r"(addr));
}
__device__ __forceinline__ void mma16816(float* c, const uint32_t* a,
                                         uint32_t b0, uint32_t b1) {
    asm volatile(
        "mma.sync.aligned.m16n8k16.row.col.f32.f16.f16.f32 "
        "{%0,%1,%2,%3}, {%4,%5,%6,%7}, {%8,%9}, {%0,%1,%2,%3};"
        : "+f"(c[0]), "+f"(c[1]), "+f"(c[2]), "+f"(c[3])
        : "r"(a[0]), "r"(a[1]), "r"(a[2]), "r"(a[3]), "r"(b0), "r"(b1));
}

__device__ __forceinline__ uint32_t pack2h(float a, float b) {
    __half2 h = __floats2half2_rn(a, b);
    return *(uint32_t*)&h;
}

// -------------------- router ------------------------------------------------
__global__ void zero_cnt_kernel() {
    if (threadIdx.x < E_NUM) g_cnt[threadIdx.x] = 0;
}

__global__ void router_kernel(const float* __restrict__ x,
                              const float* __restrict__ Wn,
                              const float* __restrict__ bn, int T) {
    int gw   = (blockIdx.x * blockDim.x + threadIdx.x) >> 5;
    int lane = threadIdx.x & 31;
    if (gw >= T) return;
    const float* xr = x + (size_t)gw * D_DIM;
    float acc[E_NUM];
#pragma unroll
    for (int e = 0; e < E_NUM; e++) acc[e] = 0.f;
    for (int d = lane; d < D_DIM; d += 32) {
        float xv = xr[d];
#pragma unroll
        for (int e = 0; e < E_NUM; e++) acc[e] += xv * Wn[d * E_NUM + e];
    }
#pragma unroll
    for (int off = 16; off; off >>= 1)
#pragma unroll
        for (int e = 0; e < E_NUM; e++)
            acc[e] += __shfl_xor_sync(0xffffffffu, acc[e], off);

    if (lane == 0) {
        float v[E_NUM];
#pragma unroll
        for (int e = 0; e < E_NUM; e++) v[e] = acc[e] + bn[e];
        int i0 = 0;
#pragma unroll
        for (int e = 1; e < E_NUM; e++) if (v[e] > v[i0]) i0 = e;
        int i1 = (i0 == 0) ? 1 : 0;
#pragma unroll
        for (int e = 0; e < E_NUM; e++)
            if (e != i0 && v[e] > v[i1]) i1 = e;
        float ex = expf(v[i1] - v[i0]);
        float g0 = 1.f / (1.f + ex);
        float g1 = ex / (1.f + ex);
        int p0 = atomicAdd(&g_cnt[i0], 1);
        int p1 = atomicAdd(&g_cnt[i1], 1);
        int b = gw * 2;
        g_topi[b] = i0; g_topi[b + 1] = i1;
        g_gate[b] = g0; g_gate[b + 1] = g1;
        g_pos[b]  = p0; g_pos[b + 1]  = p1;
    }
}

__global__ void scan_kernel() {
    if (threadIdx.x == 0) {
        int s = 0;
        for (int e = 0; e < E_NUM; e++) { g_off[e] = s; s += g_cnt[e]; }
    }
}

__global__ void build_kernel(int T) {
    int i = blockIdx.x * blockDim.x + threadIdx.x;
    if (i >= T * 2) return;
    int e = g_topi[i];
    int slot = g_off[e] + g_pos[i];
    g_slot[i] = slot;
    g_rowtok[slot]  = i >> 1;
    g_rowgate[slot] = g_gate[i];
}

// -------------------- conversions ------------------------------------------
__global__ void convert_kernel(const float* __restrict__ src,
                               __half* __restrict__ dst, size_t n8) {
    size_t i = (size_t)blockIdx.x * blockDim.x + threadIdx.x;
    if (i >= n8) return;
    float4 v0 = ((const float4*)src)[i * 2];
    float4 v1 = ((const float4*)src)[i * 2 + 1];
    uint4 h;
    h.x = pack2h(v0.x, v0.y);
    h.y = pack2h(v0.z, v0.w);
    h.z = pack2h(v1.x, v1.y);
    h.w = pack2h(v1.z, v1.w);
    ((uint4*)dst)[i] = h;
}

__global__ void gatherx_kernel(const float* __restrict__ x) {
    int slot = blockIdx.x;
    int d = threadIdx.x * 4;
    float4 v = *(const float4*)(x + (size_t)g_rowtok[slot] * D_DIM + d);
    uint2 h;
    h.x = pack2h(v.x, v.y);
    h.y = pack2h(v.z, v.w);
    ((uint2*)g_xh)[((size_t)slot * D_DIM + d) >> 2] = h;
}

// -------------------- grouped GEMM (fp16 mma.sync, f32 accum) ---------------
#define A_OFF 0
#define B_OFF 16384
#define STAGE_BYTES 32768
#define NSTAGE 3
#define SMEM_DYN (NSTAGE * STAGE_BYTES)

template<int KDIM, int NDIM, bool RELU>
__global__ __launch_bounds__(256, 2)
void moe_gemm_kernel(const __half* __restrict__ Ah,
                     const __half* __restrict__ Bh,
                     const float* __restrict__ bias,
                     __half* __restrict__ Ch,    // GEMM1 out (fp16)
                     float* __restrict__ Cf) {   // GEMM2 out (fp32)
    const int e   = blockIdx.z;
    const int cnt = g_cnt[e];
    const int m0  = blockIdx.y * 128;
    if (m0 >= cnt) return;
    const int base = g_off[e];
    const int n0   = blockIdx.x * 128;
    const int tid  = threadIdx.x;
    const int wid  = tid >> 5;
    const int lane = tid & 31;
    const int wm   = wid & 1;    // warp row (64 rows)
    const int wn   = wid >> 1;   // warp col (32 cols)

    extern __shared__ char smem[];
    const uint32_t sb = smem_u32(smem);

    const __half* Be = Bh + (size_t)e * KDIM * NDIM;

    // staging: 4 x 16B per operand per thread (256 thr covers 16KB each)
    size_t a_go[4], b_go[4];
    uint32_t a_sw[4], b_sw[4];
#pragma unroll
    for (int i = 0; i < 4; i++) {
        int idx = tid + i * 256;
        int ar = idx >> 3, kg = idx & 7;           // A: 128 rows x 8 x 16B
        int am = m0 + ar; if (am >= cnt) am = cnt - 1;
        a_go[i] = (size_t)(base + am) * KDIM + kg * 8;
        a_sw[i] = SW128(ar * 128 + kg * 16);
        int bh = idx >> 9, rem = idx & 511;        // B: 2 halves x 64k x 8 x 16B
        int bk = rem >> 3, bn = rem & 7;
        b_go[i] = (size_t)bk * NDIM + n0 + bh * 64 + bn * 8;
        b_sw[i] = bh * 8192 + SW128(bk * 128 + bn * 16);
    }

    auto issue = [&](int c) {
        uint32_t st = sb + (c % NSTAGE) * STAGE_BYTES;
        const __half* pa = Ah + (size_t)c * 64;
        const __half* pb = Be + (size_t)c * 64 * NDIM;
#pragma unroll
        for (int i = 0; i < 4; i++) {
            CPASYNC16(st + A_OFF + a_sw[i], pa + a_go[i]);
            CPASYNC16(st + B_OFF + b_sw[i], pb + b_go[i]);
        }
        CPCOMMIT();
    };

    float C[4][4][4];    // [mt 16rows][n8 frag][quad]
#pragma unroll
    for (int i = 0; i < 4; i++)
#pragma unroll
        for (int j = 0; j < 4; j++)
#pragma unroll
            for (int q = 0; q < 4; q++) C[i][j][q] = 0.f;

    constexpr int CHUNKS = KDIM / 64;
    const int g  = lane >> 3;       // ldmatrix lane group
    const int lr = lane & 7;

    issue(0); issue(1);
    for (int c = 0; c < CHUNKS; c++) {
        if (c + 1 < CHUNKS) CPWAIT1(); else CPWAIT0();
        __syncthreads();            // stage c ready; stage (c-1)%3 readers done
        if (c + 2 < CHUNKS) issue(c + 2);
        uint32_t st = sb + (c % NSTAGE) * STAGE_BYTES;

#pragma unroll
        for (int ks = 0; ks < 4; ks++) {
            uint32_t a[4][4];
#pragma unroll
            for (int mt = 0; mt < 4; mt++) {
                int row = wm * 64 + mt * 16 + (g & 1) * 8 + lr;
                int col = ks * 16 + (g >> 1) * 8;
                ldsm_x4(a[mt], st + A_OFF + SW128(row * 128 + col * 2));
            }
            uint32_t b[2][4];
#pragma unroll
            for (int nt = 0; nt < 2; nt++) {
                int kk = ks * 16 + (g & 1) * 8 + lr;
                int nn = wn * 32 + nt * 16 + (g >> 1) * 8;
                int bhalf = nn >> 6;
                ldsm_x4_t(b[nt], st + B_OFF + bhalf * 8192 +
                                  SW128(kk * 128 + (nn & 63) * 2));
            }
#pragma unroll
            for (int mt = 0; mt < 4; mt++)
#pragma unroll
                for (int nt = 0; nt < 2; nt++)
#pragma unroll
                    for (int s = 0; s < 2; s++)
                        mma16816(C[mt][nt * 2 + s], a[mt],
                                 b[nt][s * 2], b[nt][s * 2 + 1]);
        }
    }

    // -------- epilogue
    const int qr = lane >> 2, qc = lane & 3;
#pragma unroll
    for (int mt = 0; mt < 4; mt++) {
#pragma unroll
        for (int j = 0; j < 4; j++) {
            int col = n0 + wn * 32 + j * 8 + qc * 2;
            float b0 = bias[e * NDIM + col];
            float b1 = bias[e * NDIM + col + 1];
#pragma unroll
            for (int h = 0; h < 2; h++) {
                int lrow = wm * 64 + mt * 16 + qr + h * 8;
                if (m0 + lrow >= cnt) continue;
                int gr = base + m0 + lrow;
                float v0 = C[mt][j][h * 2 + 0] + b0;
                float v1 = C[mt][j][h * 2 + 1] + b1;
                if (RELU) {
                    v0 = v0 > 0.f ? v0 : 0.f;
                    v1 = v1 > 0.f ? v1 : 0.f;
                    ((uint32_t*)Ch)[((size_t)gr * NDIM + col) >> 1] = pack2h(v0, v1);
                } else {
                    float gate = g_rowgate[gr];
                    float2 o2 = make_float2(gate * v0, gate * v1);
                    *(float2*)(Cf + (size_t)gr * NDIM + col) = o2;
                }
            }
        }
    }
}

// -------------------- combine ----------------------------------------------
__global__ void combine_kernel(float* __restrict__ out, int T) {
    int i = blockIdx.x * blockDim.x + threadIdx.x;          // float4 index
    if (i >= T * (D_DIM / 4)) return;
    int t  = i >> 8;                 // / (D_DIM/4)
    int d4 = i & (D_DIM / 4 - 1);
    size_t r0 = (size_t)g_slot[t * 2]     * (D_DIM / 4) + d4;
    size_t r1 = (size_t)g_slot[t * 2 + 1] * (D_DIM / 4) + d4;
    float4 a = ((const float4*)g_y)[r0];
    float4 b = ((const float4*)g_y)[r1];
    ((float4*)out)[i] = make_float4(a.x + b.x, a.y + b.y, a.z + b.z, a.w + b.w);
}

// -------------------- launch ------------------------------------------------
extern "C" void kernel_launch(void* const* d_in, const int* in_sizes, int n_in,
                              void* d_out, int out_size) {
    const float* x  = (const float*)d_in[0];
    const float* Wn = (const float*)d_in[1];
    const float* bn = (const float*)d_in[2];
    const float* W1 = (const float*)d_in[3];
    const float* b1 = (const float*)d_in[4];
    const float* W2 = (const float*)d_in[5];
    const float* b2 = (const float*)d_in[6];
    const int T = in_sizes[0] / D_DIM;

    cudaFuncSetAttribute(moe_gemm_kernel<D_DIM, F_DIM, true>,
                         cudaFuncAttributeMaxDynamicSharedMemorySize, SMEM_DYN);
    cudaFuncSetAttribute(moe_gemm_kernel<F_DIM, D_DIM, false>,
                         cudaFuncAttributeMaxDynamicSharedMemorySize, SMEM_DYN);

    __half *w1h, *w2h, *xh, *hh;
    float* yptr;
    cudaGetSymbolAddress((void**)&w1h, g_w1h);
    cudaGetSymbolAddress((void**)&w2h, g_w2h);
    cudaGetSymbolAddress((void**)&xh, g_xh);
    cudaGetSymbolAddress((void**)&hh, g_hh);
    cudaGetSymbolAddress((void**)&yptr, g_y);

    zero_cnt_kernel<<<1, 32>>>();
    router_kernel<<<(T * 32 + 255) / 256, 256>>>(x, Wn, bn, T);
    scan_kernel<<<1, 32>>>();
    build_kernel<<<(T * 2 + 255) / 256, 256>>>(T);
    gatherx_kernel<<<T * 2, 256>>>(x);

    const size_t wn8 = (size_t)E_NUM * D_DIM * F_DIM / 8;
    convert_kernel<<<(unsigned)((wn8 + 255) / 256), 256>>>(W1, w1h, wn8);
    convert_kernel<<<(unsigned)((wn8 + 255) / 256), 256>>>(W2, w2h, wn8);

    const int MT = (MAXT + 127) / 128;  // worst case: one expert takes all tokens
    dim3 g1(F_DIM / 128, MT, E_NUM);
    moe_gemm_kernel<D_DIM, F_DIM, true><<<g1, 256, SMEM_DYN>>>(
        xh, w1h, b1, hh, nullptr);
    dim3 g2(D_DIM / 128, MT, E_NUM);
    moe_gemm_kernel<F_DIM, D_DIM, false><<<g2, 256, SMEM_DYN>>>(
        hh, w2h, b2, nullptr, yptr);

    combine_kernel<<<(T * (D_DIM / 4) + 255) / 256, 256>>>((float*)d_out, T);
}

// round 10
// speedup vs baseline: 2.4633x; 1.0216x over previous
#include <cuda_runtime.h>
#include <cuda_fp16.h>
#include <math.h>
#include <stdint.h>

// SparseMoE: T=2048, D=1024, F=4096, E=8, top-2.
// router -> convert weights to fp16 (W2 first: keeps W1 L2-hot for GEMM1) ->
// build+gather fused -> grouped GEMM1 (fp16 mma.sync f32-acc, relu) ->
// grouped GEMM2 (fp16, +bias, *gate) -> combine.
// GEMM: 128x128 tile, 256 thr (8 warps, 2x4, 64x32/warp), 3-stage ring,
// 2 CTAs/SM, ks-level B-fragment double buffering.

#define D_DIM 1024
#define E_NUM 8
#define F_DIM 4096
#define MAXT  2048
#define MAXROWS (2 * MAXT)

// -------------------- device scratch (no cudaMalloc allowed) ---------------
__device__ __half g_w1h[(size_t)E_NUM * D_DIM * F_DIM];
__device__ __half g_w2h[(size_t)E_NUM * F_DIM * D_DIM];
__device__ __half g_xh[(size_t)MAXROWS * D_DIM];
__device__ __half g_hh[(size_t)MAXROWS * F_DIM];
__device__ float g_y[(size_t)MAXROWS * D_DIM];
__device__ int   g_cnt[E_NUM];
__device__ int   g_off[E_NUM];
__device__ int   g_topi[MAXT * 2];
__device__ float g_gate[MAXT * 2];
__device__ int   g_pos[MAXT * 2];
__device__ int   g_slot[MAXT * 2];
__device__ float g_rowgate[MAXROWS];

// -------------------- helpers ----------------------------------------------
__device__ __forceinline__ uint32_t smem_u32(const void* p) {
    uint32_t a;
    asm("{ .reg .u64 t; cvta.to.shared.u64 t, %1; cvt.u32.u64 %0, t; }"
        : "=r"(a) : "l"(p));
    return a;
}

#define SW128(o) ((uint32_t)(o) ^ ((((uint32_t)(o)) >> 3) & 0x70u))

#define CPASYNC16(s, g) \
    asm volatile("cp.async.cg.shared.global [%0], [%1], 16;" \
        :: "r"((uint32_t)(s)), "l"(g) : "memory")
#define CPCOMMIT() asm volatile("cp.async.commit_group;" ::: "memory")
#define CPWAIT1()  asm volatile("cp.async.wait_group 1;" ::: "memory")
#define CPWAIT0()  asm volatile("cp.async.wait_group 0;" ::: "memory")

__device__ __forceinline__ void ldsm_x4(uint32_t* r, uint32_t addr) {
    asm volatile("ldmatrix.sync.aligned.m8n8.x4.shared.b16 {%0,%1,%2,%3}, [%4];"
        : "=r"(r[0]), "=r"(r[1]), "=r"(r[2]), "=r"(r[3]) : "r"(addr));
}
__device__ __forceinline__ void ldsm_x4_t(uint32_t* r, uint32_t addr) {
    asm volatile("ldmatrix.sync.aligned.m8n8.x4.trans.shared.b16 {%0,%1,%2,%3}, [%4];"
        : "=r"(r[0]), "=r"(r[1]), "=r"(r[2]), "=r"(r[3]) : "r"(addr));
}
__device__ __forceinline__ void mma16816(float* c, const uint32_t* a,
                                         uint32_t b0, uint32_t b1) {
    asm volatile(
        "mma.sync.aligned.m16n8k16.row.col.f32.f16.f16.f32 "
        "{%0,%1,%2,%3}, {%4,%5,%6,%7}, {%8,%9}, {%0,%1,%2,%3};"
        : "+f"(c[0]), "+f"(c[1]), "+f"(c[2]), "+f"(c[3])
        : "r"(a[0]), "r"(a[1]), "r"(a[2]), "r"(a[3]), "r"(b0), "r"(b1));
}

__device__ __forceinline__ uint32_t pack2h(float a, float b) {
    __half2 h = __floats2half2_rn(a, b);
    return *(uint32_t*)&h;
}

// -------------------- router ------------------------------------------------
__global__ void zero_cnt_kernel() {
    if (threadIdx.x < E_NUM) g_cnt[threadIdx.x] = 0;
}

__global__ void router_kernel(const float* __restrict__ x,
                              const float* __restrict__ Wn,
                              const float* __restrict__ bn, int T) {
    int gw   = (blockIdx.x * blockDim.x + threadIdx.x) >> 5;
    int lane = threadIdx.x & 31;
    if (gw >= T) return;
    const float* xr = x + (size_t)gw * D_DIM;
    float acc[E_NUM];
#pragma unroll
    for (int e = 0; e < E_NUM; e++) acc[e] = 0.f;
    for (int d = lane; d < D_DIM; d += 32) {
        float xv = xr[d];
#pragma unroll
        for (int e = 0; e < E_NUM; e++) acc[e] += xv * Wn[d * E_NUM + e];
    }
#pragma unroll
    for (int off = 16; off; off >>= 1)
#pragma unroll
        for (int e = 0; e < E_NUM; e++)
            acc[e] += __shfl_xor_sync(0xffffffffu, acc[e], off);

    if (lane == 0) {
        float v[E_NUM];
#pragma unroll
        for (int e = 0; e < E_NUM; e++) v[e] = acc[e] + bn[e];
        int i0 = 0;
#pragma unroll
        for (int e = 1; e < E_NUM; e++) if (v[e] > v[i0]) i0 = e;
        int i1 = (i0 == 0) ? 1 : 0;
#pragma unroll
        for (int e = 0; e < E_NUM; e++)
            if (e != i0 && v[e] > v[i1]) i1 = e;
        float ex = expf(v[i1] - v[i0]);
        float g0 = 1.f / (1.f + ex);
        float g1 = ex / (1.f + ex);
        int p0 = atomicAdd(&g_cnt[i0], 1);
        int p1 = atomicAdd(&g_cnt[i1], 1);
        int b = gw * 2;
        g_topi[b] = i0; g_topi[b + 1] = i1;
        g_gate[b] = g0; g_gate[b + 1] = g1;
        g_pos[b]  = p0; g_pos[b + 1]  = p1;
    }
}

__global__ void scan_kernel() {
    if (threadIdx.x == 0) {
        int s = 0;
        for (int e = 0; e < E_NUM; e++) { g_off[e] = s; s += g_cnt[e]; }
    }
}

// fused build + gather: block i handles assignment i (slot bookkeeping +
// fp16 row copy into slot-major g_xh)
__global__ void build_gather_kernel(const float* __restrict__ x) {
    int i = blockIdx.x;
    __shared__ int s_slot;
    if (threadIdx.x == 0) {
        int e    = g_topi[i];
        int slot = g_off[e] + g_pos[i];
        g_slot[i]       = slot;
        g_rowgate[slot] = g_gate[i];
        s_slot = slot;
    }
    __syncthreads();
    int slot = s_slot;
    int tok  = i >> 1;
    int d    = threadIdx.x * 4;
    float4 v = *(const float4*)(x + (size_t)tok * D_DIM + d);
    uint2 h;
    h.x = pack2h(v.x, v.y);
    h.y = pack2h(v.z, v.w);
    ((uint2*)g_xh)[((size_t)slot * D_DIM + d) >> 2] = h;
}

// -------------------- conversions ------------------------------------------
__global__ void convert_kernel(const float* __restrict__ src,
                               __half* __restrict__ dst, size_t n8) {
    size_t i = (size_t)blockIdx.x * blockDim.x + threadIdx.x;
    if (i >= n8) return;
    float4 v0 = ((const float4*)src)[i * 2];
    float4 v1 = ((const float4*)src)[i * 2 + 1];
    uint4 h;
    h.x = pack2h(v0.x, v0.y);
    h.y = pack2h(v0.z, v0.w);
    h.z = pack2h(v1.x, v1.y);
    h.w = pack2h(v1.z, v1.w);
    ((uint4*)dst)[i] = h;
}

// -------------------- grouped GEMM (fp16 mma.sync, f32 accum) ---------------
#define A_OFF 0
#define B_OFF 16384
#define STAGE_BYTES 32768
#define NSTAGE 3
#define SMEM_DYN (NSTAGE * STAGE_BYTES)

template<int KDIM, int NDIM, bool RELU>
__global__ __launch_bounds__(256, 2)
void moe_gemm_kernel(const __half* __restrict__ Ah,
                     const __half* __restrict__ Bh,
                     const float* __restrict__ bias,
                     __half* __restrict__ Ch,    // GEMM1 out (fp16)
                     float* __restrict__ Cf) {   // GEMM2 out (fp32)
    const int e   = blockIdx.z;
    const int cnt = g_cnt[e];
    const int m0  = blockIdx.y * 128;
    if (m0 >= cnt) return;
    const int base = g_off[e];
    const int n0   = blockIdx.x * 128;
    const int tid  = threadIdx.x;
    const int wid  = tid >> 5;
    const int lane = tid & 31;
    const int wm   = wid & 1;    // warp row (64 rows)
    const int wn   = wid >> 1;   // warp col (32 cols)

    extern __shared__ char smem[];
    const uint32_t sb = smem_u32(smem);

    const __half* Be = Bh + (size_t)e * KDIM * NDIM;

    // staging: 4 x 16B per operand per thread (256 thr covers 16KB each)
    size_t a_go[4], b_go[4];
    uint32_t a_sw[4], b_sw[4];
#pragma unroll
    for (int i = 0; i < 4; i++) {
        int idx = tid + i * 256;
        int ar = idx >> 3, kg = idx & 7;           // A: 128 rows x 8 x 16B
        int am = m0 + ar; if (am >= cnt) am = cnt - 1;
        a_go[i] = (size_t)(base + am) * KDIM + kg * 8;
        a_sw[i] = SW128(ar * 128 + kg * 16);
        int bh = idx >> 9, rem = idx & 511;        // B: 2 halves x 64k x 8 x 16B
        int bk = rem >> 3, bn = rem & 7;
        b_go[i] = (size_t)bk * NDIM + n0 + bh * 64 + bn * 8;
        b_sw[i] = bh * 8192 + SW128(bk * 128 + bn * 16);
    }

    auto issue = [&](int c) {
        uint32_t st = sb + (c % NSTAGE) * STAGE_BYTES;
        const __half* pa = Ah + (size_t)c * 64;
        const __half* pb = Be + (size_t)c * 64 * NDIM;
#pragma unroll
        for (int i = 0; i < 4; i++) {
            CPASYNC16(st + A_OFF + a_sw[i], pa + a_go[i]);
            CPASYNC16(st + B_OFF + b_sw[i], pb + b_go[i]);
        }
        CPCOMMIT();
    };

    float C[4][4][4];    // [mt 16rows][n8 frag][quad]
#pragma unroll
    for (int i = 0; i < 4; i++)
#pragma unroll
        for (int j = 0; j < 4; j++)
#pragma unroll
            for (int q = 0; q < 4; q++) C[i][j][q] = 0.f;

    constexpr int CHUNKS = KDIM / 64;
    const int g  = lane >> 3;       // ldmatrix lane group
    const int lr = lane & 7;

    // B fragment addresses per ks (double-buffered at ks level)
    auto loadB = [&](uint32_t st, int ks, uint32_t (*bf)[4]) {
#pragma unroll
        for (int nt = 0; nt < 2; nt++) {
            int kk = ks * 16 + (g & 1) * 8 + lr;
            int nn = wn * 32 + nt * 16 + (g >> 1) * 8;
            int bhalf = nn >> 6;
            ldsm_x4_t(bf[nt], st + B_OFF + bhalf * 8192 +
                              SW128(kk * 128 + (nn & 63) * 2));
        }
    };

    issue(0); issue(1);
    for (int c = 0; c < CHUNKS; c++) {
        if (c + 1 < CHUNKS) CPWAIT1(); else CPWAIT0();
        __syncthreads();            // stage c ready; stage (c-1)%3 readers done
        if (c + 2 < CHUNKS) issue(c + 2);
        uint32_t st = sb + (c % NSTAGE) * STAGE_BYTES;

        uint32_t bfr[2][2][4];      // [parity][nt][frag]
        loadB(st, 0, bfr[0]);
#pragma unroll
        for (int ks = 0; ks < 4; ks++) {
            if (ks < 3) loadB(st, ks + 1, bfr[(ks + 1) & 1]);
            uint32_t a[4][4];
#pragma unroll
            for (int mt = 0; mt < 4; mt++) {
                int row = wm * 64 + mt * 16 + (g & 1) * 8 + lr;
                int col = ks * 16 + (g >> 1) * 8;
                ldsm_x4(a[mt], st + A_OFF + SW128(row * 128 + col * 2));
            }
            uint32_t (*b)[4] = bfr[ks & 1];
#pragma unroll
            for (int mt = 0; mt < 4; mt++)
#pragma unroll
                for (int nt = 0; nt < 2; nt++)
#pragma unroll
                    for (int s = 0; s < 2; s++)
                        mma16816(C[mt][nt * 2 + s], a[mt],
                                 b[nt][s * 2], b[nt][s * 2 + 1]);
        }
    }

    // -------- epilogue
    const int qr = lane >> 2, qc = lane & 3;
    float bb0[4], bb1[4];
#pragma unroll
    for (int j = 0; j < 4; j++) {
        int col = n0 + wn * 32 + j * 8 + qc * 2;
        bb0[j] = bias[e * NDIM + col];
        bb1[j] = bias[e * NDIM + col + 1];
    }
#pragma unroll
    for (int mt = 0; mt < 4; mt++) {
#pragma unroll
        for (int j = 0; j < 4; j++) {
            int col = n0 + wn * 32 + j * 8 + qc * 2;
#pragma unroll
            for (int h = 0; h < 2; h++) {
                int lrow = wm * 64 + mt * 16 + qr + h * 8;
                if (m0 + lrow >= cnt) continue;
                int gr = base + m0 + lrow;
                float v0 = C[mt][j][h * 2 + 0] + bb0[j];
                float v1 = C[mt][j][h * 2 + 1] + bb1[j];
                if (RELU) {
                    v0 = v0 > 0.f ? v0 : 0.f;
                    v1 = v1 > 0.f ? v1 : 0.f;
                    ((uint32_t*)Ch)[((size_t)gr * NDIM + col) >> 1] = pack2h(v0, v1);
                } else {
                    float gate = g_rowgate[gr];
                    float2 o2 = make_float2(gate * v0, gate * v1);
                    *(float2*)(Cf + (size_t)gr * NDIM + col) = o2;
                }
            }
        }
    }
}

// -------------------- combine ----------------------------------------------
__global__ void combine_kernel(float* __restrict__ out, int T) {
    int i = blockIdx.x * blockDim.x + threadIdx.x;          // float4 index
    if (i >= T * (D_DIM / 4)) return;
    int t  = i >> 8;                 // / (D_DIM/4)
    int d4 = i & (D_DIM / 4 - 1);
    size_t r0 = (size_t)g_slot[t * 2]     * (D_DIM / 4) + d4;
    size_t r1 = (size_t)g_slot[t * 2 + 1] * (D_DIM / 4) + d4;
    float4 a = ((const float4*)g_y)[r0];
    float4 b = ((const float4*)g_y)[r1];
    ((float4*)out)[i] = make_float4(a.x + b.x, a.y + b.y, a.z + b.z, a.w + b.w);
}

// -------------------- launch ------------------------------------------------
extern "C" void kernel_launch(void* const* d_in, const int* in_sizes, int n_in,
                              void* d_out, int out_size) {
    const float* x  = (const float*)d_in[0];
    const float* Wn = (const float*)d_in[1];
    const float* bn = (const float*)d_in[2];
    const float* W1 = (const float*)d_in[3];
    const float* b1 = (const float*)d_in[4];
    const float* W2 = (const float*)d_in[5];
    const float* b2 = (const float*)d_in[6];
    const int T = in_sizes[0] / D_DIM;

    cudaFuncSetAttribute(moe_gemm_kernel<D_DIM, F_DIM, true>,
                         cudaFuncAttributeMaxDynamicSharedMemorySize, SMEM_DYN);
    cudaFuncSetAttribute(moe_gemm_kernel<F_DIM, D_DIM, false>,
                         cudaFuncAttributeMaxDynamicSharedMemorySize, SMEM_DYN);

    __half *w1h, *w2h, *xh, *hh;
    float* yptr;
    cudaGetSymbolAddress((void**)&w1h, g_w1h);
    cudaGetSymbolAddress((void**)&w2h, g_w2h);
    cudaGetSymbolAddress((void**)&xh, g_xh);
    cudaGetSymbolAddress((void**)&hh, g_hh);
    cudaGetSymbolAddress((void**)&yptr, g_y);

    zero_cnt_kernel<<<1, 32>>>();
    router_kernel<<<(T * 32 + 255) / 256, 256>>>(x, Wn, bn, T);
    scan_kernel<<<1, 32>>>();
    build_gather_kernel<<<T * 2, 256>>>(x);

    // W2 first so W1 fp16 stays L2-resident when GEMM1 starts.
    const size_t wn8 = (size_t)E_NUM * D_DIM * F_DIM / 8;
    convert_kernel<<<(unsigned)((wn8 + 255) / 256), 256>>>(W2, w2h, wn8);
    convert_kernel<<<(unsigned)((wn8 + 255) / 256), 256>>>(W1, w1h, wn8);

    const int MT = (MAXT + 127) / 128;  // worst case: one expert takes all tokens
    dim3 g1(F_DIM / 128, MT, E_NUM);
    moe_gemm_kernel<D_DIM, F_DIM, true><<<g1, 256, SMEM_DYN>>>(
        xh, w1h, b1, hh, nullptr);
    dim3 g2(D_DIM / 128, MT, E_NUM);
    moe_gemm_kernel<F_DIM, D_DIM, false><<<g2, 256, SMEM_DYN>>>(
        hh, w2h, b2, nullptr, yptr);

    combine_kernel<<<(T * (D_DIM / 4) + 255) / 256, 256>>>((float*)d_out, T);
}

// round 11
// speedup vs baseline: 2.4784x; 1.0061x over previous
#include <cuda_runtime.h>
#include <cuda_fp16.h>
#include <math.h>
#include <stdint.h>

// SparseMoE: T=2048, D=1024, F=4096, E=8, top-2.
// memset(cnt) -> fused convert W1+W2 to fp16 -> router -> build+gather
// (inline scan) -> grouped GEMM1 (fp16 mma.sync f32-acc, relu) ->
// grouped GEMM2 (fp16, +bias, *gate) -> combine.
// GEMM: 128x128 tile, 256 thr (8 warps, 2x4, 64x32/warp), 3-stage ring,
// 2 CTAs/SM, ks-level B-fragment double buffering.

#define D_DIM 1024
#define E_NUM 8
#define F_DIM 4096
#define MAXT  2048
#define MAXROWS (2 * MAXT)

// -------------------- device scratch (no cudaMalloc allowed) ---------------
__device__ __half g_w1h[(size_t)E_NUM * D_DIM * F_DIM];
__device__ __half g_w2h[(size_t)E_NUM * F_DIM * D_DIM];
__device__ __half g_xh[(size_t)MAXROWS * D_DIM];
__device__ __half g_hh[(size_t)MAXROWS * F_DIM];
__device__ float g_y[(size_t)MAXROWS * D_DIM];
__device__ int   g_cnt[E_NUM];
__device__ int   g_topi[MAXT * 2];
__device__ float g_gate[MAXT * 2];
__device__ int   g_pos[MAXT * 2];
__device__ int   g_slot[MAXT * 2];
__device__ float g_rowgate[MAXROWS];

// -------------------- helpers ----------------------------------------------
__device__ __forceinline__ uint32_t smem_u32(const void* p) {
    uint32_t a;
    asm("{ .reg .u64 t; cvta.to.shared.u64 t, %1; cvt.u32.u64 %0, t; }"
        : "=r"(a) : "l"(p));
    return a;
}

#define SW128(o) ((uint32_t)(o) ^ ((((uint32_t)(o)) >> 3) & 0x70u))

#define CPASYNC16(s, g) \
    asm volatile("cp.async.cg.shared.global [%0], [%1], 16;" \
        :: "r"((uint32_t)(s)), "l"(g) : "memory")
#define CPCOMMIT() asm volatile("cp.async.commit_group;" ::: "memory")
#define CPWAIT1()  asm volatile("cp.async.wait_group 1;" ::: "memory")
#define CPWAIT0()  asm volatile("cp.async.wait_group 0;" ::: "memory")

__device__ __forceinline__ void ldsm_x4(uint32_t* r, uint32_t addr) {
    asm volatile("ldmatrix.sync.aligned.m8n8.x4.shared.b16 {%0,%1,%2,%3}, [%4];"
        : "=r"(r[0]), "=r"(r[1]), "=r"(r[2]), "=r"(r[3]) : "r"(addr));
}
__device__ __forceinline__ void ldsm_x4_t(uint32_t* r, uint32_t addr) {
    asm volatile("ldmatrix.sync.aligned.m8n8.x4.trans.shared.b16 {%0,%1,%2,%3}, [%4];"
        : "=r"(r[0]), "=r"(r[1]), "=r"(r[2]), "=r"(r[3]) : "r"(addr));
}
__device__ __forceinline__ void mma16816(float* c, const uint32_t* a,
                                         uint32_t b0, uint32_t b1) {
    asm volatile(
        "mma.sync.aligned.m16n8k16.row.col.f32.f16.f16.f32 "
        "{%0,%1,%2,%3}, {%4,%5,%6,%7}, {%8,%9}, {%0,%1,%2,%3};"
        : "+f"(c[0]), "+f"(c[1]), "+f"(c[2]), "+f"(c[3])
        : "r"(a[0]), "r"(a[1]), "r"(a[2]), "r"(a[3]), "r"(b0), "r"(b1));
}

__device__ __forceinline__ uint32_t pack2h(float a, float b) {
    __half2 h = __floats2half2_rn(a, b);
    return *(uint32_t*)&h;
}

// -------------------- fused weight convert (W1 then W2 in one grid) --------
__global__ void convert_both_kernel(const float* __restrict__ W1,
                                    const float* __restrict__ W2,
                                    __half* __restrict__ w1h,
                                    __half* __restrict__ w2h, size_t n8) {
    size_t i = (size_t)blockIdx.x * blockDim.x + threadIdx.x;
    const float* src;
    __half* dst;
    size_t j;
    if (i < n8) { src = W1; dst = w1h; j = i; }
    else if (i < 2 * n8) { src = W2; dst = w2h; j = i - n8; }
    else return;
    float4 v0 = ((const float4*)src)[j * 2];
    float4 v1 = ((const float4*)src)[j * 2 + 1];
    uint4 h;
    h.x = pack2h(v0.x, v0.y);
    h.y = pack2h(v0.z, v0.w);
    h.z = pack2h(v1.x, v1.y);
    h.w = pack2h(v1.z, v1.w);
    ((uint4*)dst)[j] = h;
}

// -------------------- router ------------------------------------------------
__global__ void router_kernel(const float* __restrict__ x,
                              const float* __restrict__ Wn,
                              const float* __restrict__ bn, int T) {
    int gw   = (blockIdx.x * blockDim.x + threadIdx.x) >> 5;
    int lane = threadIdx.x & 31;
    if (gw >= T) return;
    const float* xr = x + (size_t)gw * D_DIM;
    float acc[E_NUM];
#pragma unroll
    for (int e = 0; e < E_NUM; e++) acc[e] = 0.f;
    for (int d = lane; d < D_DIM; d += 32) {
        float xv = xr[d];
#pragma unroll
        for (int e = 0; e < E_NUM; e++) acc[e] += xv * Wn[d * E_NUM + e];
    }
#pragma unroll
    for (int off = 16; off; off >>= 1)
#pragma unroll
        for (int e = 0; e < E_NUM; e++)
            acc[e] += __shfl_xor_sync(0xffffffffu, acc[e], off);

    if (lane == 0) {
        float v[E_NUM];
#pragma unroll
        for (int e = 0; e < E_NUM; e++) v[e] = acc[e] + bn[e];
        int i0 = 0;
#pragma unroll
        for (int e = 1; e < E_NUM; e++) if (v[e] > v[i0]) i0 = e;
        int i1 = (i0 == 0) ? 1 : 0;
#pragma unroll
        for (int e = 0; e < E_NUM; e++)
            if (e != i0 && v[e] > v[i1]) i1 = e;
        float ex = expf(v[i1] - v[i0]);
        float g0 = 1.f / (1.f + ex);
        float g1 = ex / (1.f + ex);
        int p0 = atomicAdd(&g_cnt[i0], 1);
        int p1 = atomicAdd(&g_cnt[i1], 1);
        int b = gw * 2;
        g_topi[b] = i0; g_topi[b + 1] = i1;
        g_gate[b] = g0; g_gate[b + 1] = g1;
        g_pos[b]  = p0; g_pos[b + 1]  = p1;
    }
}

// fused build + gather: block i handles assignment i; prefix sum over
// g_cnt (8 values) computed inline.
__global__ void build_gather_kernel(const float* __restrict__ x) {
    int i = blockIdx.x;
    __shared__ int s_slot;
    if (threadIdx.x == 0) {
        int e = g_topi[i];
        int base = 0;
#pragma unroll
        for (int j = 0; j < E_NUM; j++)
            if (j < e) base += g_cnt[j];
        int slot = base + g_pos[i];
        g_slot[i]       = slot;
        g_rowgate[slot] = g_gate[i];
        s_slot = slot;
    }
    __syncthreads();
    int slot = s_slot;
    int tok  = i >> 1;
    int d    = threadIdx.x * 4;
    float4 v = *(const float4*)(x + (size_t)tok * D_DIM + d);
    uint2 h;
    h.x = pack2h(v.x, v.y);
    h.y = pack2h(v.z, v.w);
    ((uint2*)g_xh)[((size_t)slot * D_DIM + d) >> 2] = h;
}

// -------------------- grouped GEMM (fp16 mma.sync, f32 accum) ---------------
#define A_OFF 0
#define B_OFF 16384
#define STAGE_BYTES 32768
#define NSTAGE 3
#define SMEM_DYN (NSTAGE * STAGE_BYTES)

template<int KDIM, int NDIM, bool RELU>
__global__ __launch_bounds__(256, 2)
void moe_gemm_kernel(const __half* __restrict__ Ah,
                     const __half* __restrict__ Bh,
                     const float* __restrict__ bias,
                     __half* __restrict__ Ch,    // GEMM1 out (fp16)
                     float* __restrict__ Cf) {   // GEMM2 out (fp32)
    const int e   = blockIdx.z;
    const int cnt = g_cnt[e];
    const int m0  = blockIdx.y * 128;
    if (m0 >= cnt) return;
    int base = 0;
#pragma unroll
    for (int j = 0; j < E_NUM; j++)
        if (j < e) base += g_cnt[j];
    const int n0   = blockIdx.x * 128;
    const int tid  = threadIdx.x;
    const int wid  = tid >> 5;
    const int lane = tid & 31;
    const int wm   = wid & 1;    // warp row (64 rows)
    const int wn   = wid >> 1;   // warp col (32 cols)

    extern __shared__ char smem[];
    const uint32_t sb = smem_u32(smem);

    const __half* Be = Bh + (size_t)e * KDIM * NDIM;

    // staging: 4 x 16B per operand per thread (256 thr covers 16KB each)
    size_t a_go[4], b_go[4];
    uint32_t a_sw[4], b_sw[4];
#pragma unroll
    for (int i = 0; i < 4; i++) {
        int idx = tid + i * 256;
        int ar = idx >> 3, kg = idx & 7;           // A: 128 rows x 8 x 16B
        int am = m0 + ar; if (am >= cnt) am = cnt - 1;
        a_go[i] = (size_t)(base + am) * KDIM + kg * 8;
        a_sw[i] = SW128(ar * 128 + kg * 16);
        int bh = idx >> 9, rem = idx & 511;        // B: 2 halves x 64k x 8 x 16B
        int bk = rem >> 3, bn = rem & 7;
        b_go[i] = (size_t)bk * NDIM + n0 + bh * 64 + bn * 8;
        b_sw[i] = bh * 8192 + SW128(bk * 128 + bn * 16);
    }

    auto issue = [&](int c) {
        uint32_t st = sb + (c % NSTAGE) * STAGE_BYTES;
        const __half* pa = Ah + (size_t)c * 64;
        const __half* pb = Be + (size_t)c * 64 * NDIM;
#pragma unroll
        for (int i = 0; i < 4; i++) {
            CPASYNC16(st + A_OFF + a_sw[i], pa + a_go[i]);
            CPASYNC16(st + B_OFF + b_sw[i], pb + b_go[i]);
        }
        CPCOMMIT();
    };

    float C[4][4][4];    // [mt 16rows][n8 frag][quad]
#pragma unroll
    for (int i = 0; i < 4; i++)
#pragma unroll
        for (int j = 0; j < 4; j++)
#pragma unroll
            for (int q = 0; q < 4; q++) C[i][j][q] = 0.f;

    constexpr int CHUNKS = KDIM / 64;
    const int g  = lane >> 3;       // ldmatrix lane group
    const int lr = lane & 7;

    auto loadB = [&](uint32_t st, int ks, uint32_t (*bf)[4]) {
#pragma unroll
        for (int nt = 0; nt < 2; nt++) {
            int kk = ks * 16 + (g & 1) * 8 + lr;
            int nn = wn * 32 + nt * 16 + (g >> 1) * 8;
            int bhalf = nn >> 6;
            ldsm_x4_t(bf[nt], st + B_OFF + bhalf * 8192 +
                              SW128(kk * 128 + (nn & 63) * 2));
        }
    };

    issue(0); issue(1);
    for (int c = 0; c < CHUNKS; c++) {
        if (c + 1 < CHUNKS) CPWAIT1(); else CPWAIT0();
        __syncthreads();            // stage c ready; stage (c-1)%3 readers done
        if (c + 2 < CHUNKS) issue(c + 2);
        uint32_t st = sb + (c % NSTAGE) * STAGE_BYTES;

        uint32_t bfr[2][2][4];      // [parity][nt][frag]
        loadB(st, 0, bfr[0]);
#pragma unroll
        for (int ks = 0; ks < 4; ks++) {
            if (ks < 3) loadB(st, ks + 1, bfr[(ks + 1) & 1]);
            uint32_t a[4][4];
#pragma unroll
            for (int mt = 0; mt < 4; mt++) {
                int row = wm * 64 + mt * 16 + (g & 1) * 8 + lr;
                int col = ks * 16 + (g >> 1) * 8;
                ldsm_x4(a[mt], st + A_OFF + SW128(row * 128 + col * 2));
            }
            uint32_t (*b)[4] = bfr[ks & 1];
#pragma unroll
            for (int mt = 0; mt < 4; mt++)
#pragma unroll
                for (int nt = 0; nt < 2; nt++)
#pragma unroll
                    for (int s = 0; s < 2; s++)
                        mma16816(C[mt][nt * 2 + s], a[mt],
                                 b[nt][s * 2], b[nt][s * 2 + 1]);
        }
    }

    // -------- epilogue
    const int qr = lane >> 2, qc = lane & 3;
    float bb0[4], bb1[4];
#pragma unroll
    for (int j = 0; j < 4; j++) {
        int col = n0 + wn * 32 + j * 8 + qc * 2;
        bb0[j] = bias[e * NDIM + col];
        bb1[j] = bias[e * NDIM + col + 1];
    }
#pragma unroll
    for (int mt = 0; mt < 4; mt++) {
#pragma unroll
        for (int j = 0; j < 4; j++) {
            int col = n0 + wn * 32 + j * 8 + qc * 2;
#pragma unroll
            for (int h = 0; h < 2; h++) {
                int lrow = wm * 64 + mt * 16 + qr + h * 8;
                if (m0 + lrow >= cnt) continue;
                int gr = base + m0 + lrow;
                float v0 = C[mt][j][h * 2 + 0] + bb0[j];
                float v1 = C[mt][j][h * 2 + 1] + bb1[j];
                if (RELU) {
                    v0 = v0 > 0.f ? v0 : 0.f;
                    v1 = v1 > 0.f ? v1 : 0.f;
                    ((uint32_t*)Ch)[((size_t)gr * NDIM + col) >> 1] = pack2h(v0, v1);
                } else {
                    float gate = g_rowgate[gr];
                    float2 o2 = make_float2(gate * v0, gate * v1);
                    *(float2*)(Cf + (size_t)gr * NDIM + col) = o2;
                }
            }
        }
    }
}

// -------------------- combine ----------------------------------------------
__global__ void combine_kernel(float* __restrict__ out, int T) {
    int i = blockIdx.x * blockDim.x + threadIdx.x;          // float4 index
    if (i >= T * (D_DIM / 4)) return;
    int t  = i >> 8;                 // / (D_DIM/4)
    int d4 = i & (D_DIM / 4 - 1);
    size_t r0 = (size_t)g_slot[t * 2]     * (D_DIM / 4) + d4;
    size_t r1 = (size_t)g_slot[t * 2 + 1] * (D_DIM / 4) + d4;
    float4 a = ((const float4*)g_y)[r0];
    float4 b = ((const float4*)g_y)[r1];
    ((float4*)out)[i] = make_float4(a.x + b.x, a.y + b.y, a.z + b.z, a.w + b.w);
}

// -------------------- launch ------------------------------------------------
extern "C" void kernel_launch(void* const* d_in, const int* in_sizes, int n_in,
                              void* d_out, int out_size) {
    const float* x  = (const float*)d_in[0];
    const float* Wn = (const float*)d_in[1];
    const float* bn = (const float*)d_in[2];
    const float* W1 = (const float*)d_in[3];
    const float* b1 = (const float*)d_in[4];
    const float* W2 = (const float*)d_in[5];
    const float* b2 = (const float*)d_in[6];
    const int T = in_sizes[0] / D_DIM;

    cudaFuncSetAttribute(moe_gemm_kernel<D_DIM, F_DIM, true>,
                         cudaFuncAttributeMaxDynamicSharedMemorySize, SMEM_DYN);
    cudaFuncSetAttribute(moe_gemm_kernel<F_DIM, D_DIM, false>,
                         cudaFuncAttributeMaxDynamicSharedMemorySize, SMEM_DYN);

    __half *w1h, *w2h, *xh, *hh;
    float* yptr;
    int* cntptr;
    cudaGetSymbolAddress((void**)&w1h, g_w1h);
    cudaGetSymbolAddress((void**)&w2h, g_w2h);
    cudaGetSymbolAddress((void**)&xh, g_xh);
    cudaGetSymbolAddress((void**)&hh, g_hh);
    cudaGetSymbolAddress((void**)&yptr, g_y);
    cudaGetSymbolAddress((void**)&cntptr, g_cnt);

    // memset node (not a kernel launch): zero expert counters
    cudaMemsetAsync(cntptr, 0, E_NUM * sizeof(int), 0);

    // kernel 1: fused weight convert (W1 and W2 in one grid)
    const size_t wn8 = (size_t)E_NUM * D_DIM * F_DIM / 8;
    convert_both_kernel<<<(unsigned)((2 * wn8 + 255) / 256), 256>>>(
        W1, W2, w1h, w2h, wn8);

    // kernel 2: router
    router_kernel<<<(T * 32 + 255) / 256, 256>>>(x, Wn, bn, T);

    // kernel 3: build + gather (inline scan over 8 counters)
    build_gather_kernel<<<T * 2, 256>>>(x);

    // kernel 4: GEMM1 (gets ncu's profile slot)
    const int MT = (MAXT + 127) / 128;  // worst case: one expert takes all tokens
    dim3 g1(F_DIM / 128, MT, E_NUM);
    moe_gemm_kernel<D_DIM, F_DIM, true><<<g1, 256, SMEM_DYN>>>(
        xh, w1h, b1, hh, nullptr);

    // kernel 5: GEMM2
    dim3 g2(D_DIM / 128, MT, E_NUM);
    moe_gemm_kernel<F_DIM, D_DIM, false><<<g2, 256, SMEM_DYN>>>(
        hh, w2h, b2, nullptr, yptr);

    // kernel 6: combine
    combine_kernel<<<(T * (D_DIM / 4) + 255) / 256, 256>>>((float*)d_out, T);
}

// round 12
// speedup vs baseline: 2.5024x; 1.0097x over previous
#include <cuda_runtime.h>
#include <cuda_fp16.h>
#include <math.h>
#include <stdint.h>

// SparseMoE: T=2048, D=1024, F=4096, E=8, top-2.
// memset(cnt,out) -> router -> [build+gather || convert W1] ->
// [GEMM1 (fp16 mma.sync, relu) || convert W2] -> GEMM2 (atomic out, +b2, *gate).
// GEMM: 128x128 tile, 256 thr (8 warps, 2x4, 64x32/warp), 3-stage ring,
// 2 CTAs/SM, ks-level B-fragment double buffering. Grid-role fusion for the
// HBM-bound converts (no extra streams; graph-capture safe).

#define D_DIM 1024
#define E_NUM 8
#define F_DIM 4096
#define MAXT  2048
#define MAXROWS (2 * MAXT)

// -------------------- device scratch (no cudaMalloc allowed) ---------------
__device__ __half g_w1h[(size_t)E_NUM * D_DIM * F_DIM];
__device__ __half g_w2h[(size_t)E_NUM * F_DIM * D_DIM];
__device__ __half g_xh[(size_t)MAXROWS * D_DIM];
__device__ __half g_hh[(size_t)MAXROWS * F_DIM];
__device__ int   g_cnt[E_NUM];
__device__ int   g_topi[MAXT * 2];
__device__ float g_gate[MAXT * 2];
__device__ int   g_pos[MAXT * 2];
__device__ int   g_rowtok[MAXROWS];
__device__ float g_rowgate[MAXROWS];

// -------------------- helpers ----------------------------------------------
__device__ __forceinline__ uint32_t smem_u32(const void* p) {
    uint32_t a;
    asm("{ .reg .u64 t; cvta.to.shared.u64 t, %1; cvt.u32.u64 %0, t; }"
        : "=r"(a) : "l"(p));
    return a;
}

#define SW128(o) ((uint32_t)(o) ^ ((((uint32_t)(o)) >> 3) & 0x70u))

#define CPASYNC16(s, g) \
    asm volatile("cp.async.cg.shared.global [%0], [%1], 16;" \
        :: "r"((uint32_t)(s)), "l"(g) : "memory")
#define CPCOMMIT() asm volatile("cp.async.commit_group;" ::: "memory")
#define CPWAIT1()  asm volatile("cp.async.wait_group 1;" ::: "memory")
#define CPWAIT0()  asm volatile("cp.async.wait_group 0;" ::: "memory")

__device__ __forceinline__ void ldsm_x4(uint32_t* r, uint32_t addr) {
    asm volatile("ldmatrix.sync.aligned.m8n8.x4.shared.b16 {%0,%1,%2,%3}, [%4];"
        : "=r"(r[0]), "=r"(r[1]), "=r"(r[2]), "=r"(r[3]) : "r"(addr));
}
__device__ __forceinline__ void ldsm_x4_t(uint32_t* r, uint32_t addr) {
    asm volatile("ldmatrix.sync.aligned.m8n8.x4.trans.shared.b16 {%0,%1,%2,%3}, [%4];"
        : "=r"(r[0]), "=r"(r[1]), "=r"(r[2]), "=r"(r[3]) : "r"(addr));
}
__device__ __forceinline__ void mma16816(float* c, const uint32_t* a,
                                         uint32_t b0, uint32_t b1) {
    asm volatile(
        "mma.sync.aligned.m16n8k16.row.col.f32.f16.f16.f32 "
        "{%0,%1,%2,%3}, {%4,%5,%6,%7}, {%8,%9}, {%0,%1,%2,%3};"
        : "+f"(c[0]), "+f"(c[1]), "+f"(c[2]), "+f"(c[3])
        : "r"(a[0]), "r"(a[1]), "r"(a[2]), "r"(a[3]), "r"(b0), "r"(b1));
}

__device__ __forceinline__ uint32_t pack2h(float a, float b) {
    __half2 h = __floats2half2_rn(a, b);
    return *(uint32_t*)&h;
}

__device__ __forceinline__ void cvt_u4(const float* __restrict__ src,
                                       __half* __restrict__ dst, size_t j) {
    float4 v0 = ((const float4*)src)[j * 2];
    float4 v1 = ((const float4*)src)[j * 2 + 1];
    uint4 h;
    h.x = pack2h(v0.x, v0.y);
    h.y = pack2h(v0.z, v0.w);
    h.z = pack2h(v1.x, v1.y);
    h.w = pack2h(v1.z, v1.w);
    ((uint4*)dst)[j] = h;
}

// -------------------- router ------------------------------------------------
__global__ void router_kernel(const float* __restrict__ x,
                              const float* __restrict__ Wn,
                              const float* __restrict__ bn, int T) {
    int gw   = (blockIdx.x * blockDim.x + threadIdx.x) >> 5;
    int lane = threadIdx.x & 31;
    if (gw >= T) return;
    const float* xr = x + (size_t)gw * D_DIM;
    float acc[E_NUM];
#pragma unroll
    for (int e = 0; e < E_NUM; e++) acc[e] = 0.f;
    for (int d = lane; d < D_DIM; d += 32) {
        float xv = xr[d];
#pragma unroll
        for (int e = 0; e < E_NUM; e++) acc[e] += xv * Wn[d * E_NUM + e];
    }
#pragma unroll
    for (int off = 16; off; off >>= 1)
#pragma unroll
        for (int e = 0; e < E_NUM; e++)
            acc[e] += __shfl_xor_sync(0xffffffffu, acc[e], off);

    if (lane == 0) {
        float v[E_NUM];
#pragma unroll
        for (int e = 0; e < E_NUM; e++) v[e] = acc[e] + bn[e];
        int i0 = 0;
#pragma unroll
        for (int e = 1; e < E_NUM; e++) if (v[e] > v[i0]) i0 = e;
        int i1 = (i0 == 0) ? 1 : 0;
#pragma unroll
        for (int e = 0; e < E_NUM; e++)
            if (e != i0 && v[e] > v[i1]) i1 = e;
        float ex = expf(v[i1] - v[i0]);
        float g0 = 1.f / (1.f + ex);
        float g1 = ex / (1.f + ex);
        int p0 = atomicAdd(&g_cnt[i0], 1);
        int p1 = atomicAdd(&g_cnt[i1], 1);
        int b = gw * 2;
        g_topi[b] = i0; g_topi[b + 1] = i1;
        g_gate[b] = g0; g_gate[b + 1] = g1;
        g_pos[b]  = p0; g_pos[b + 1]  = p1;
    }
}

// -------------------- fused: build+gather (blocks [0,T*2)) + convert W1 ----
// Convert role: blocks [T*2, T*2 + NCONV1): 256 thr x 1 uint4 (8 halfs) each.
__global__ void gather_conv_kernel(const float* __restrict__ x,
                                   const float* __restrict__ W1,
                                   __half* __restrict__ w1h, int T2) {
    int b = blockIdx.x;
    if (b >= T2) {
        size_t j = (size_t)(b - T2) * 256 + threadIdx.x;  // uint4 index
        cvt_u4(W1, w1h, j);
        return;
    }
    __shared__ int s_slot;
    if (threadIdx.x == 0) {
        int e = g_topi[b];
        int base = 0;
#pragma unroll
        for (int j = 0; j < E_NUM; j++)
            if (j < e) base += g_cnt[j];
        int slot = base + g_pos[b];
        g_rowtok[slot]  = b >> 1;
        g_rowgate[slot] = g_gate[b];
        s_slot = slot;
    }
    __syncthreads();
    int slot = s_slot;
    int tok  = b >> 1;
    int d    = threadIdx.x * 4;
    float4 v = *(const float4*)(x + (size_t)tok * D_DIM + d);
    uint2 h;
    h.x = pack2h(v.x, v.y);
    h.y = pack2h(v.z, v.w);
    ((uint2*)g_xh)[((size_t)slot * D_DIM + d) >> 2] = h;
}

// -------------------- grouped GEMM (fp16 mma.sync, f32 accum) ---------------
// FUSECONV: z==0 slice converts W2 (csrc->cdst) instead of GEMM work.
// RELU=true: writes fp16 h. RELU=false: atomicAdd gate*(acc+bias) into Cf[tok].
#define A_OFF 0
#define B_OFF 16384
#define STAGE_BYTES 32768
#define NSTAGE 3
#define SMEM_DYN (NSTAGE * STAGE_BYTES)

template<int KDIM, int NDIM, bool RELU, bool FUSECONV>
__global__ __launch_bounds__(256, 2)
void moe_gemm_kernel(const __half* __restrict__ Ah,
                     const __half* __restrict__ Bh,
                     const float* __restrict__ bias,
                     __half* __restrict__ Ch,
                     float* __restrict__ Cf,
                     const float* __restrict__ csrc,
                     __half* __restrict__ cdst) {
    int zz = blockIdx.z;
    if (FUSECONV) {
        if (zz == 0) {
            // convert W2: 512 CTAs x 256 thr x 32 uint4 = 33.55M halfs
            size_t cta = (size_t)blockIdx.y * gridDim.x + blockIdx.x;
            size_t base = cta * 8192 + threadIdx.x;   // uint4 index
#pragma unroll
            for (int it = 0; it < 32; it++)
                cvt_u4(csrc, cdst, base + (size_t)it * 256);
            return;
        }
        zz -= 1;
    }
    const int e   = zz;
    const int cnt = g_cnt[e];
    const int m0  = blockIdx.y * 128;
    if (m0 >= cnt) return;
    int base = 0;
#pragma unroll
    for (int j = 0; j < E_NUM; j++)
        if (j < e) base += g_cnt[j];
    const int n0   = blockIdx.x * 128;
    const int tid  = threadIdx.x;
    const int wid  = tid >> 5;
    const int lane = tid & 31;
    const int wm   = wid & 1;    // warp row (64 rows)
    const int wn   = wid >> 1;   // warp col (32 cols)

    extern __shared__ char smem[];
    const uint32_t sb = smem_u32(smem);

    const __half* Be = Bh + (size_t)e * KDIM * NDIM;

    // staging: 4 x 16B per operand per thread (256 thr covers 16KB each)
    size_t a_go[4], b_go[4];
    uint32_t a_sw[4], b_sw[4];
#pragma unroll
    for (int i = 0; i < 4; i++) {
        int idx = tid + i * 256;
        int ar = idx >> 3, kg = idx & 7;           // A: 128 rows x 8 x 16B
        int am = m0 + ar; if (am >= cnt) am = cnt - 1;
        a_go[i] = (size_t)(base + am) * KDIM + kg * 8;
        a_sw[i] = SW128(ar * 128 + kg * 16);
        int bh = idx >> 9, rem = idx & 511;        // B: 2 halves x 64k x 8 x 16B
        int bk = rem >> 3, bn = rem & 7;
        b_go[i] = (size_t)bk * NDIM + n0 + bh * 64 + bn * 8;
        b_sw[i] = bh * 8192 + SW128(bk * 128 + bn * 16);
    }

    auto issue = [&](int c) {
        uint32_t st = sb + (c % NSTAGE) * STAGE_BYTES;
        const __half* pa = Ah + (size_t)c * 64;
        const __half* pb = Be + (size_t)c * 64 * NDIM;
#pragma unroll
        for (int i = 0; i < 4; i++) {
            CPASYNC16(st + A_OFF + a_sw[i], pa + a_go[i]);
            CPASYNC16(st + B_OFF + b_sw[i], pb + b_go[i]);
        }
        CPCOMMIT();
    };

    float C[4][4][4];    // [mt 16rows][n8 frag][quad]
#pragma unroll
    for (int i = 0; i < 4; i++)
#pragma unroll
        for (int j = 0; j < 4; j++)
#pragma unroll
            for (int q = 0; q < 4; q++) C[i][j][q] = 0.f;

    constexpr int CHUNKS = KDIM / 64;
    const int g  = lane >> 3;       // ldmatrix lane group
    const int lr = lane & 7;

    auto loadB = [&](uint32_t st, int ks, uint32_t (*bf)[4]) {
#pragma unroll
        for (int nt = 0; nt < 2; nt++) {
            int kk = ks * 16 + (g & 1) * 8 + lr;
            int nn = wn * 32 + nt * 16 + (g >> 1) * 8;
            int bhalf = nn >> 6;
            ldsm_x4_t(bf[nt], st + B_OFF + bhalf * 8192 +
                              SW128(kk * 128 + (nn & 63) * 2));
        }
    };

    issue(0); issue(1);
    for (int c = 0; c < CHUNKS; c++) {
        if (c + 1 < CHUNKS) CPWAIT1(); else CPWAIT0();
        __syncthreads();            // stage c ready; stage (c-1)%3 readers done
        if (c + 2 < CHUNKS) issue(c + 2);
        uint32_t st = sb + (c % NSTAGE) * STAGE_BYTES;

        uint32_t bfr[2][2][4];      // [parity][nt][frag]
        loadB(st, 0, bfr[0]);
#pragma unroll
        for (int ks = 0; ks < 4; ks++) {
            if (ks < 3) loadB(st, ks + 1, bfr[(ks + 1) & 1]);
            uint32_t a[4][4];
#pragma unroll
            for (int mt = 0; mt < 4; mt++) {
                int row = wm * 64 + mt * 16 + (g & 1) * 8 + lr;
                int col = ks * 16 + (g >> 1) * 8;
                ldsm_x4(a[mt], st + A_OFF + SW128(row * 128 + col * 2));
            }
            uint32_t (*b)[4] = bfr[ks & 1];
#pragma unroll
            for (int mt = 0; mt < 4; mt++)
#pragma unroll
                for (int nt = 0; nt < 2; nt++)
#pragma unroll
                    for (int s = 0; s < 2; s++)
                        mma16816(C[mt][nt * 2 + s], a[mt],
                                 b[nt][s * 2], b[nt][s * 2 + 1]);
        }
    }

    // -------- epilogue
    const int qr = lane >> 2, qc = lane & 3;
    float bb0[4], bb1[4];
#pragma unroll
    for (int j = 0; j < 4; j++) {
        int col = n0 + wn * 32 + j * 8 + qc * 2;
        bb0[j] = bias[e * NDIM + col];
        bb1[j] = bias[e * NDIM + col + 1];
    }
#pragma unroll
    for (int mt = 0; mt < 4; mt++) {
#pragma unroll
        for (int j = 0; j < 4; j++) {
            int col = n0 + wn * 32 + j * 8 + qc * 2;
#pragma unroll
            for (int h = 0; h < 2; h++) {
                int lrow = wm * 64 + mt * 16 + qr + h * 8;
                if (m0 + lrow >= cnt) continue;
                int gr = base + m0 + lrow;
                float v0 = C[mt][j][h * 2 + 0] + bb0[j];
                float v1 = C[mt][j][h * 2 + 1] + bb1[j];
                if (RELU) {
                    v0 = v0 > 0.f ? v0 : 0.f;
                    v1 = v1 > 0.f ? v1 : 0.f;
                    ((uint32_t*)Ch)[((size_t)gr * NDIM + col) >> 1] = pack2h(v0, v1);
                } else {
                    int tok = g_rowtok[gr];
                    float gate = g_rowgate[gr];
                    float* op = Cf + (size_t)tok * NDIM + col;
                    atomicAdd(op,     gate * v0);   // exactly 2 commutative
                    atomicAdd(op + 1, gate * v1);   // fp32 adds per element
                }
            }
        }
    }
}

// -------------------- launch ------------------------------------------------
extern "C" void kernel_launch(void* const* d_in, const int* in_sizes, int n_in,
                              void* d_out, int out_size) {
    const float* x  = (const float*)d_in[0];
    const float* Wn = (const float*)d_in[1];
    const float* bn = (const float*)d_in[2];
    const float* W1 = (const float*)d_in[3];
    const float* b1 = (const float*)d_in[4];
    const float* W2 = (const float*)d_in[5];
    const float* b2 = (const float*)d_in[6];
    const int T = in_sizes[0] / D_DIM;

    cudaFuncSetAttribute(moe_gemm_kernel<D_DIM, F_DIM, true, true>,
                         cudaFuncAttributeMaxDynamicSharedMemorySize, SMEM_DYN);
    cudaFuncSetAttribute(moe_gemm_kernel<F_DIM, D_DIM, false, false>,
                         cudaFuncAttributeMaxDynamicSharedMemorySize, SMEM_DYN);

    __half *w1h, *w2h, *xh, *hh;
    int* cntptr;
    cudaGetSymbolAddress((void**)&w1h, g_w1h);
    cudaGetSymbolAddress((void**)&w2h, g_w2h);
    cudaGetSymbolAddress((void**)&xh, g_xh);
    cudaGetSymbolAddress((void**)&hh, g_hh);
    cudaGetSymbolAddress((void**)&cntptr, g_cnt);

    // memset nodes: zero expert counters and output accumulator
    cudaMemsetAsync(cntptr, 0, E_NUM * sizeof(int), 0);
    cudaMemsetAsync(d_out, 0, (size_t)out_size * sizeof(float), 0);

    // kernel 1: router
    router_kernel<<<(T * 32 + 255) / 256, 256>>>(x, Wn, bn, T);

    // kernel 2: fused build+gather (needs router) || convert W1
    const int NCONV1 = (int)((size_t)E_NUM * D_DIM * F_DIM / 8 / 256); // 16384
    gather_conv_kernel<<<T * 2 + NCONV1, 256>>>(x, W1, w1h, T * 2);

    // kernel 3: GEMM1 (z=1..8) || convert W2 (z=0)
    const int MT = (MAXT + 127) / 128;
    dim3 g1(F_DIM / 128, MT, E_NUM + 1);
    moe_gemm_kernel<D_DIM, F_DIM, true, true><<<g1, 256, SMEM_DYN>>>(
        xh, w1h, b1, hh, nullptr, W2, w2h);

    // kernel 4: GEMM2 (atomic accumulate into d_out)
    dim3 g2(D_DIM / 128, MT, E_NUM);
    moe_gemm_kernel<F_DIM, D_DIM, false, false><<<g2, 256, SMEM_DYN>>>(
        hh, w2h, b2, nullptr, (float*)d_out, nullptr, nullptr);
}